// round 1
// baseline (speedup 1.0000x reference)
#include <cuda_runtime.h>
#include <math.h>

// Problem constants
#define TOK   2048      // B*S tokens
#define DDIM  1024
#define FDIM  4096
#define NEXP  8
#define FSH   512       // shared-expert hidden
#define TOPK  2
#define ROWCAP (NEXP*TOK)       // 16384 capacity rows for routed experts (region e: [e*TOK, e*TOK+cnt))
#define NROWS  (ROWCAP + TOK)   // + shared rows

// ---- scratch (device globals; no runtime allocation) ----
__device__ int   g_cnt[NEXP];
__device__ int   g_tok[ROWCAP];            // token id per compacted row
__device__ int   g_rowof[TOK * TOPK];      // token -> its K compacted rows
__device__ float g_gw[TOK * TOPK];         // token -> its K gate probs
__device__ float g_h[(size_t)NROWS * FDIM];    // silu(x@w1)*(x@w3), per row
__device__ float g_orow[(size_t)NROWS * DDIM]; // (h @ w2), per row

// ============================ reset =====================================
__global__ void k_reset() {
    if (threadIdx.x < NEXP) g_cnt[threadIdx.x] = 0;
}

// ============================ gating ====================================
// one warp per token: 8 dot products of length 1024, softmax, top-2, compact.
__global__ void k_gate(const float* __restrict__ x, const float* __restrict__ gateW) {
    int gwarp = (blockIdx.x * blockDim.x + threadIdx.x) >> 5;
    int lane  = threadIdx.x & 31;
    if (gwarp >= TOK) return;
    const float* xr = x + (size_t)gwarp * DDIM;
    float xv[32];
#pragma unroll
    for (int i = 0; i < 32; i++) xv[i] = xr[lane + 32 * i];

    float logit[NEXP];
#pragma unroll
    for (int e = 0; e < NEXP; e++) {
        const float* wr = gateW + e * DDIM;
        float acc = 0.f;
#pragma unroll
        for (int i = 0; i < 32; i++) acc += xv[i] * wr[lane + 32 * i];
#pragma unroll
        for (int o = 16; o > 0; o >>= 1) acc += __shfl_xor_sync(0xffffffffu, acc, o);
        logit[e] = acc;
    }
    if (lane == 0) {
        float m = logit[0];
#pragma unroll
        for (int e = 1; e < NEXP; e++) m = fmaxf(m, logit[e]);
        float p[NEXP], den = 0.f;
#pragma unroll
        for (int e = 0; e < NEXP; e++) { p[e] = expf(logit[e] - m); den += p[e]; }
        // top-2 (ties -> lowest index, matching lax.top_k)
        int i1 = 0;
#pragma unroll
        for (int e = 1; e < NEXP; e++) if (p[e] > p[i1]) i1 = e;
        int i2 = (i1 == 0) ? 1 : 0;
#pragma unroll
        for (int e = 0; e < NEXP; e++) if (e != i2 && e != i1 && p[e] > p[i2]) i2 = e;

        int pos1 = atomicAdd(&g_cnt[i1], 1);
        int r1 = i1 * TOK + pos1;
        g_tok[r1] = gwarp;
        g_rowof[2 * gwarp + 0] = r1;
        g_gw[2 * gwarp + 0] = p[i1] / den;

        int pos2 = atomicAdd(&g_cnt[i2], 1);
        int r2 = i2 * TOK + pos2;
        g_tok[r2] = gwarp;
        g_rowof[2 * gwarp + 1] = r2;
        g_gw[2 * gwarp + 1] = p[i2] / den;
    }
}

// ============================ GEMM tiles ================================
#define BM 128
#define BN 64
#define BK 16
#define TM 8
#define TN 4
// 256 threads: tx = tid%16 covers N (16*4=64), ty = tid/16 covers M (16*8=128)

// GEMM1: h[row, n] = silu(x_row . w1[:,n]) * (x_row . w3[:,n])
// grid: (FDIM/BN, TOK/BM, NEXP+1). z<8: routed expert z (gathered rows); z==8: shared (concat).
__global__ __launch_bounds__(256) void k_gemm1(
    const float* __restrict__ x,
    const float* __restrict__ w1e, const float* __restrict__ w3e,
    const float* __restrict__ w1s, const float* __restrict__ w3s)
{
    const int z  = blockIdx.z;
    const int m0 = blockIdx.y * BM;
    const int n0 = blockIdx.x * BN;

    __shared__ int stok[BM];
    const float *Bg, *Bu;
    int ldb;
    size_t rowbase;

    if (z < NEXP) {
        int M = g_cnt[z];
        if (m0 >= M) return;
        Bg = w1e + (size_t)z * DDIM * FDIM + n0;
        Bu = w3e + (size_t)z * DDIM * FDIM + n0;
        ldb = FDIM;
        rowbase = (size_t)z * TOK + m0;
        if (threadIdx.x < BM) stok[threadIdx.x] = g_tok[z * TOK + m0 + threadIdx.x];
    } else {
        int nb = n0 / FSH, f0 = n0 % FSH;   // 64 | 512 -> tile within one shared-expert block
        Bg = w1s + (size_t)nb * DDIM * FSH + f0;
        Bu = w3s + (size_t)nb * DDIM * FSH + f0;
        ldb = FSH;
        rowbase = (size_t)ROWCAP + m0;
        if (threadIdx.x < BM) stok[threadIdx.x] = m0 + threadIdx.x;
    }
    __syncthreads();

    __shared__ __align__(16) float As[BK][BM];
    __shared__ __align__(16) float Bgs[BK][BN];
    __shared__ __align__(16) float Bus[BK][BN];

    float accg[TM][TN], accu[TM][TN];
#pragma unroll
    for (int i = 0; i < TM; i++)
#pragma unroll
        for (int j = 0; j < TN; j++) { accg[i][j] = 0.f; accu[i][j] = 0.f; }

    const int tid = threadIdx.x, tx = tid & 15, ty = tid >> 4;

    for (int k0 = 0; k0 < DDIM; k0 += BK) {
#pragma unroll
        for (int i = 0; i < 8; i++) {       // A: 128x16 = 2048 elems / 256 thr
            int idx = tid + i * 256;
            int m = idx >> 4, k = idx & 15;
            As[k][m] = x[(size_t)stok[m] * DDIM + k0 + k];
        }
#pragma unroll
        for (int i = 0; i < 4; i++) {       // B: 16x64 = 1024 elems / 256 thr, two mats
            int idx = tid + i * 256;
            int k = idx >> 6, n = idx & 63;
            Bgs[k][n] = Bg[(size_t)(k0 + k) * ldb + n];
            Bus[k][n] = Bu[(size_t)(k0 + k) * ldb + n];
        }
        __syncthreads();
#pragma unroll
        for (int k = 0; k < BK; k++) {
            float4 a0 = *reinterpret_cast<const float4*>(&As[k][ty * TM]);
            float4 a1 = *reinterpret_cast<const float4*>(&As[k][ty * TM + 4]);
            float4 bg = *reinterpret_cast<const float4*>(&Bgs[k][tx * TN]);
            float4 bu = *reinterpret_cast<const float4*>(&Bus[k][tx * TN]);
            float a[TM] = {a0.x, a0.y, a0.z, a0.w, a1.x, a1.y, a1.z, a1.w};
            float vg[TN] = {bg.x, bg.y, bg.z, bg.w};
            float vu[TN] = {bu.x, bu.y, bu.z, bu.w};
#pragma unroll
            for (int i = 0; i < TM; i++)
#pragma unroll
                for (int j = 0; j < TN; j++) {
                    accg[i][j] += a[i] * vg[j];
                    accu[i][j] += a[i] * vu[j];
                }
        }
        __syncthreads();
    }

    // epilogue: silu(g) * u
#pragma unroll
    for (int i = 0; i < TM; i++) {
        int m = ty * TM + i;
        float* hr = g_h + (rowbase + m) * (size_t)FDIM + n0 + tx * TN;
#pragma unroll
        for (int j = 0; j < TN; j++) {
            float gv = accg[i][j];
            float s = gv / (1.0f + __expf(-gv));
            hr[j] = s * accu[i][j];
        }
    }
}

// GEMM2: orow[row, n] = h_row . w2[:, n]
// grid: (DDIM/BN, TOK/BM, NEXP+1)
__global__ __launch_bounds__(256) void k_gemm2(
    const float* __restrict__ w2e, const float* __restrict__ w2s)
{
    const int z  = blockIdx.z;
    const int m0 = blockIdx.y * BM;
    const int n0 = blockIdx.x * BN;

    const float* B;
    size_t rowbase;
    if (z < NEXP) {
        int M = g_cnt[z];
        if (m0 >= M) return;
        B = w2e + (size_t)z * FDIM * DDIM + n0;
        rowbase = (size_t)z * TOK + m0;
    } else {
        B = w2s + n0;                        // w2_s flat == [4096,1024] row-major
        rowbase = (size_t)ROWCAP + m0;
    }
    const float* A = g_h + rowbase * (size_t)FDIM;

    __shared__ __align__(16) float As[BK][BM];
    __shared__ __align__(16) float Bs[BK][BN];

    float acc[TM][TN];
#pragma unroll
    for (int i = 0; i < TM; i++)
#pragma unroll
        for (int j = 0; j < TN; j++) acc[i][j] = 0.f;

    const int tid = threadIdx.x, tx = tid & 15, ty = tid >> 4;

    for (int k0 = 0; k0 < FDIM; k0 += BK) {
#pragma unroll
        for (int i = 0; i < 8; i++) {
            int idx = tid + i * 256;
            int m = idx >> 4, k = idx & 15;
            As[k][m] = A[(size_t)m * FDIM + k0 + k];
        }
#pragma unroll
        for (int i = 0; i < 4; i++) {
            int idx = tid + i * 256;
            int k = idx >> 6, n = idx & 63;
            Bs[k][n] = B[(size_t)(k0 + k) * DDIM + n];
        }
        __syncthreads();
#pragma unroll
        for (int k = 0; k < BK; k++) {
            float4 a0 = *reinterpret_cast<const float4*>(&As[k][ty * TM]);
            float4 a1 = *reinterpret_cast<const float4*>(&As[k][ty * TM + 4]);
            float4 bb = *reinterpret_cast<const float4*>(&Bs[k][tx * TN]);
            float a[TM] = {a0.x, a0.y, a0.z, a0.w, a1.x, a1.y, a1.z, a1.w};
            float bv[TN] = {bb.x, bb.y, bb.z, bb.w};
#pragma unroll
            for (int i = 0; i < TM; i++)
#pragma unroll
                for (int j = 0; j < TN; j++) acc[i][j] += a[i] * bv[j];
        }
        __syncthreads();
    }

#pragma unroll
    for (int i = 0; i < TM; i++) {
        int m = ty * TM + i;
        float* orp = g_orow + (rowbase + m) * (size_t)DDIM + n0 + tx * TN;
#pragma unroll
        for (int j = 0; j < TN; j++) orp[j] = acc[i][j];
    }
}

// ============================ combine ===================================
// out = 0.5 * shared/NS + 0.5 * sum_k gate_k * routed_k
__global__ void k_combine(float* __restrict__ out) {
    int idx = blockIdx.x * blockDim.x + threadIdx.x;
    if (idx >= TOK * DDIM) return;
    int t = idx >> 10;          // / DDIM
    int d = idx & (DDIM - 1);
    float sh = g_orow[((size_t)ROWCAP + t) * DDIM + d];
    int   r0 = g_rowof[2 * t], r1 = g_rowof[2 * t + 1];
    float v = 0.0625f * sh   // 0.5 / NS
            + 0.5f * (g_gw[2 * t] * g_orow[(size_t)r0 * DDIM + d]
                    + g_gw[2 * t + 1] * g_orow[(size_t)r1 * DDIM + d]);
    out[idx] = v;
}

// ============================ launch ====================================
extern "C" void kernel_launch(void* const* d_in, const int* in_sizes, int n_in,
                              void* d_out, int out_size) {
    const float* x   = (const float*)d_in[0];
    const float* gW  = (const float*)d_in[1];
    const float* w1e = (const float*)d_in[2];
    const float* w3e = (const float*)d_in[3];
    const float* w2e = (const float*)d_in[4];
    const float* w1s = (const float*)d_in[5];
    const float* w3s = (const float*)d_in[6];
    const float* w2s = (const float*)d_in[7];
    float* out = (float*)d_out;

    k_reset<<<1, 32>>>();
    k_gate<<<TOK / 8, 256>>>(x, gW);

    dim3 g1(FDIM / BN, TOK / BM, NEXP + 1);
    k_gemm1<<<g1, 256>>>(x, w1e, w3e, w1s, w3s);

    dim3 g2(DDIM / BN, TOK / BM, NEXP + 1);
    k_gemm2<<<g2, 256>>>(w2e, w2s);

    k_combine<<<(TOK * DDIM) / 256, 256>>>(out);
}

// round 2
// speedup vs baseline: 2.1931x; 2.1931x over previous
#include <cuda_runtime.h>
#include <cuda_bf16.h>
#include <math.h>

// Problem constants
#define TOK   2048
#define DDIM  1024
#define FDIM  4096
#define NEXP  8
#define FSH   512
#define TOPK  2
#define ROWCAP (NEXP*TOK)
#define NROWS  (ROWCAP + TOK)

// ---- scratch (device globals; no runtime allocation) ----
__device__ int   g_cnt[NEXP];
__device__ int   g_tok[ROWCAP];
__device__ int   g_rowof[TOK * TOPK];
__device__ float g_gw[TOK * TOPK];
__device__ float g_h[(size_t)NROWS * FDIM];
__device__ float g_orow[(size_t)NROWS * DDIM];

// ============================ helpers ===================================
__device__ __forceinline__ void mma_bf16(float* c, const unsigned* a, const unsigned* b) {
    asm volatile(
        "mma.sync.aligned.m16n8k16.row.col.f32.bf16.bf16.f32 "
        "{%0,%1,%2,%3},{%4,%5,%6,%7},{%8,%9},{%0,%1,%2,%3};"
        : "+f"(c[0]), "+f"(c[1]), "+f"(c[2]), "+f"(c[3])
        : "r"(a[0]), "r"(a[1]), "r"(a[2]), "r"(a[3]), "r"(b[0]), "r"(b[1]));
}

__device__ __forceinline__ void split_bf16(float v, __nv_bfloat16& h, __nv_bfloat16& l) {
    h = __float2bfloat16(v);
    l = __float2bfloat16(v - __bfloat162float(h));
}

// ============================ reset =====================================
__global__ void k_reset() {
    if (threadIdx.x < NEXP) g_cnt[threadIdx.x] = 0;
}

// ============================ gating ====================================
__global__ void k_gate(const float* __restrict__ x, const float* __restrict__ gateW) {
    int gwarp = (blockIdx.x * blockDim.x + threadIdx.x) >> 5;
    int lane  = threadIdx.x & 31;
    if (gwarp >= TOK) return;
    const float* xr = x + (size_t)gwarp * DDIM;
    float xv[32];
#pragma unroll
    for (int i = 0; i < 32; i++) xv[i] = xr[lane + 32 * i];

    float logit[NEXP];
#pragma unroll
    for (int e = 0; e < NEXP; e++) {
        const float* wr = gateW + e * DDIM;
        float acc = 0.f;
#pragma unroll
        for (int i = 0; i < 32; i++) acc += xv[i] * wr[lane + 32 * i];
#pragma unroll
        for (int o = 16; o > 0; o >>= 1) acc += __shfl_xor_sync(0xffffffffu, acc, o);
        logit[e] = acc;
    }
    if (lane == 0) {
        float m = logit[0];
#pragma unroll
        for (int e = 1; e < NEXP; e++) m = fmaxf(m, logit[e]);
        float p[NEXP], den = 0.f;
#pragma unroll
        for (int e = 0; e < NEXP; e++) { p[e] = expf(logit[e] - m); den += p[e]; }
        int i1 = 0;
#pragma unroll
        for (int e = 1; e < NEXP; e++) if (p[e] > p[i1]) i1 = e;
        int i2 = (i1 == 0) ? 1 : 0;
#pragma unroll
        for (int e = 0; e < NEXP; e++) if (e != i2 && e != i1 && p[e] > p[i2]) i2 = e;

        int pos1 = atomicAdd(&g_cnt[i1], 1);
        int r1 = i1 * TOK + pos1;
        g_tok[r1] = gwarp;
        g_rowof[2 * gwarp + 0] = r1;
        g_gw[2 * gwarp + 0] = p[i1] / den;

        int pos2 = atomicAdd(&g_cnt[i2], 1);
        int r2 = i2 * TOK + pos2;
        g_tok[r2] = gwarp;
        g_rowof[2 * gwarp + 1] = r2;
        g_gw[2 * gwarp + 1] = p[i2] / den;
    }
}

// ============================ GEMM tiles ================================
#define BM 128
#define BN 64
#define BK 32
#define LDT (BK + 2)   // 34: padded smem row (bf16 elems)

// GEMM1: h[row,n] = silu(x.w1[:,n]) * (x.w3[:,n]) via bf16x3 mma
// grid: (FDIM/BN, TOK/BM, NEXP+1)
__global__ __launch_bounds__(256) void k_gemm1(
    const float* __restrict__ x,
    const float* __restrict__ w1e, const float* __restrict__ w3e,
    const float* __restrict__ w1s, const float* __restrict__ w3s)
{
    const int z  = blockIdx.z;
    const int m0 = blockIdx.y * BM;
    const int n0 = blockIdx.x * BN;

    __shared__ int stok[BM];
    __shared__ __align__(16) __nv_bfloat16 As_hi[BM][LDT], As_lo[BM][LDT];
    __shared__ __align__(16) __nv_bfloat16 Bg_hi[BN][LDT], Bg_lo[BN][LDT];
    __shared__ __align__(16) __nv_bfloat16 Bu_hi[BN][LDT], Bu_lo[BN][LDT];

    const float *Bg, *Bu;
    int ldb;
    size_t rowbase;

    if (z < NEXP) {
        int M = g_cnt[z];
        if (m0 >= M) return;
        Bg = w1e + (size_t)z * DDIM * FDIM + n0;
        Bu = w3e + (size_t)z * DDIM * FDIM + n0;
        ldb = FDIM;
        rowbase = (size_t)z * TOK + m0;
        if (threadIdx.x < BM) stok[threadIdx.x] = g_tok[z * TOK + m0 + threadIdx.x];
    } else {
        int nb = n0 / FSH, f0 = n0 % FSH;
        Bg = w1s + (size_t)nb * DDIM * FSH + f0;
        Bu = w3s + (size_t)nb * DDIM * FSH + f0;
        ldb = FSH;
        rowbase = (size_t)ROWCAP + m0;
        if (threadIdx.x < BM) stok[threadIdx.x] = m0 + threadIdx.x;
    }
    __syncthreads();

    const int tid = threadIdx.x, lane = tid & 31, w = tid >> 5;
    const int wm = w >> 1, wn = w & 1;
    const int qr = lane >> 2, qc = lane & 3;

    float accg[2][4][4] = {}, accu[2][4][4] = {};

    const int am = tid >> 1, ak = (tid & 1) * 16;
    const int bk = tid >> 3, bn = (tid & 7) * 8;
    const float* arow = x + (size_t)stok[am] * DDIM;

    for (int k0 = 0; k0 < DDIM; k0 += BK) {
        // ---- stage A (128x32 fp32 -> bf16 hi/lo) ----
        {
            const float4* p = (const float4*)(arow + k0 + ak);
#pragma unroll
            for (int q = 0; q < 4; q++) {
                float4 v = p[q];
                __nv_bfloat16 h0, l0, h1, l1, h2, l2, h3, l3;
                split_bf16(v.x, h0, l0); split_bf16(v.y, h1, l1);
                split_bf16(v.z, h2, l2); split_bf16(v.w, h3, l3);
                __nv_bfloat162 t;
                t.x = h0; t.y = h1; *(__nv_bfloat162*)&As_hi[am][ak + 4 * q]     = t;
                t.x = h2; t.y = h3; *(__nv_bfloat162*)&As_hi[am][ak + 4 * q + 2] = t;
                t.x = l0; t.y = l1; *(__nv_bfloat162*)&As_lo[am][ak + 4 * q]     = t;
                t.x = l2; t.y = l3; *(__nv_bfloat162*)&As_lo[am][ak + 4 * q + 2] = t;
            }
        }
        // ---- stage B (2 mats, 32x64 fp32 -> transposed bf16 hi/lo) ----
        {
            const float4* pg = (const float4*)(Bg + (size_t)(k0 + bk) * ldb + bn);
            const float4* pu = (const float4*)(Bu + (size_t)(k0 + bk) * ldb + bn);
            float bvg[8], bvu[8];
            *(float4*)bvg = pg[0]; *(float4*)(bvg + 4) = pg[1];
            *(float4*)bvu = pu[0]; *(float4*)(bvu + 4) = pu[1];
#pragma unroll
            for (int j = 0; j < 8; j++) {
                __nv_bfloat16 h, l;
                split_bf16(bvg[j], h, l);
                Bg_hi[bn + j][bk] = h; Bg_lo[bn + j][bk] = l;
                split_bf16(bvu[j], h, l);
                Bu_hi[bn + j][bk] = h; Bu_lo[bn + j][bk] = l;
            }
        }
        __syncthreads();

#pragma unroll
        for (int kk = 0; kk < BK; kk += 16) {
            unsigned ahi[2][4], alo[2][4];
            const int c = kk + 2 * qc;
#pragma unroll
            for (int mt = 0; mt < 2; mt++) {
                int r = wm * 32 + mt * 16 + qr;
                ahi[mt][0] = *(const unsigned*)&As_hi[r][c];
                ahi[mt][1] = *(const unsigned*)&As_hi[r + 8][c];
                ahi[mt][2] = *(const unsigned*)&As_hi[r][c + 8];
                ahi[mt][3] = *(const unsigned*)&As_hi[r + 8][c + 8];
                alo[mt][0] = *(const unsigned*)&As_lo[r][c];
                alo[mt][1] = *(const unsigned*)&As_lo[r + 8][c];
                alo[mt][2] = *(const unsigned*)&As_lo[r][c + 8];
                alo[mt][3] = *(const unsigned*)&As_lo[r + 8][c + 8];
            }
#pragma unroll
            for (int nt = 0; nt < 4; nt++) {
                int nr = wn * 32 + nt * 8 + qr;
                unsigned bh[2], bl[2];
                // gate matrix
                bh[0] = *(const unsigned*)&Bg_hi[nr][c];
                bh[1] = *(const unsigned*)&Bg_hi[nr][c + 8];
                bl[0] = *(const unsigned*)&Bg_lo[nr][c];
                bl[1] = *(const unsigned*)&Bg_lo[nr][c + 8];
#pragma unroll
                for (int mt = 0; mt < 2; mt++) {
                    mma_bf16(accg[mt][nt], ahi[mt], bh);
                    mma_bf16(accg[mt][nt], ahi[mt], bl);
                    mma_bf16(accg[mt][nt], alo[mt], bh);
                }
                // up matrix
                bh[0] = *(const unsigned*)&Bu_hi[nr][c];
                bh[1] = *(const unsigned*)&Bu_hi[nr][c + 8];
                bl[0] = *(const unsigned*)&Bu_lo[nr][c];
                bl[1] = *(const unsigned*)&Bu_lo[nr][c + 8];
#pragma unroll
                for (int mt = 0; mt < 2; mt++) {
                    mma_bf16(accu[mt][nt], ahi[mt], bh);
                    mma_bf16(accu[mt][nt], ahi[mt], bl);
                    mma_bf16(accu[mt][nt], alo[mt], bh);
                }
            }
        }
        __syncthreads();
    }

    // epilogue: silu(g)*u -> g_h
#pragma unroll
    for (int mt = 0; mt < 2; mt++)
#pragma unroll
        for (int nt = 0; nt < 4; nt++) {
            int R = wm * 32 + mt * 16 + qr;
            int C = wn * 32 + nt * 8 + 2 * qc;
#pragma unroll
            for (int half = 0; half < 2; half++) {
                int r = R + half * 8;
                float g0 = accg[mt][nt][2 * half], g1 = accg[mt][nt][2 * half + 1];
                float u0 = accu[mt][nt][2 * half], u1 = accu[mt][nt][2 * half + 1];
                float2 o;
                o.x = g0 / (1.f + __expf(-g0)) * u0;
                o.y = g1 / (1.f + __expf(-g1)) * u1;
                *(float2*)&g_h[(rowbase + r) * (size_t)FDIM + n0 + C] = o;
            }
        }
}

// GEMM2: orow[row,n] = h_row . w2[:,n] via bf16x3 mma
// grid: (DDIM/BN, TOK/BM, NEXP+1)
__global__ __launch_bounds__(256) void k_gemm2(
    const float* __restrict__ w2e, const float* __restrict__ w2s)
{
    const int z  = blockIdx.z;
    const int m0 = blockIdx.y * BM;
    const int n0 = blockIdx.x * BN;

    __shared__ __align__(16) __nv_bfloat16 As_hi[BM][LDT], As_lo[BM][LDT];
    __shared__ __align__(16) __nv_bfloat16 Bs_hi[BN][LDT], Bs_lo[BN][LDT];

    const float* B;
    size_t rowbase;
    if (z < NEXP) {
        int M = g_cnt[z];
        if (m0 >= M) return;
        B = w2e + (size_t)z * FDIM * DDIM + n0;
        rowbase = (size_t)z * TOK + m0;
    } else {
        B = w2s + n0;
        rowbase = (size_t)ROWCAP + m0;
    }

    const int tid = threadIdx.x, lane = tid & 31, w = tid >> 5;
    const int wm = w >> 1, wn = w & 1;
    const int qr = lane >> 2, qc = lane & 3;

    float acc[2][4][4] = {};

    const int am = tid >> 1, ak = (tid & 1) * 16;
    const int bk = tid >> 3, bn = (tid & 7) * 8;
    const float* arow = g_h + (rowbase + am) * (size_t)FDIM;

    for (int k0 = 0; k0 < FDIM; k0 += BK) {
        {
            const float4* p = (const float4*)(arow + k0 + ak);
#pragma unroll
            for (int q = 0; q < 4; q++) {
                float4 v = p[q];
                __nv_bfloat16 h0, l0, h1, l1, h2, l2, h3, l3;
                split_bf16(v.x, h0, l0); split_bf16(v.y, h1, l1);
                split_bf16(v.z, h2, l2); split_bf16(v.w, h3, l3);
                __nv_bfloat162 t;
                t.x = h0; t.y = h1; *(__nv_bfloat162*)&As_hi[am][ak + 4 * q]     = t;
                t.x = h2; t.y = h3; *(__nv_bfloat162*)&As_hi[am][ak + 4 * q + 2] = t;
                t.x = l0; t.y = l1; *(__nv_bfloat162*)&As_lo[am][ak + 4 * q]     = t;
                t.x = l2; t.y = l3; *(__nv_bfloat162*)&As_lo[am][ak + 4 * q + 2] = t;
            }
        }
        {
            const float4* pb = (const float4*)(B + (size_t)(k0 + bk) * DDIM + bn);
            float bv[8];
            *(float4*)bv = pb[0]; *(float4*)(bv + 4) = pb[1];
#pragma unroll
            for (int j = 0; j < 8; j++) {
                __nv_bfloat16 h, l;
                split_bf16(bv[j], h, l);
                Bs_hi[bn + j][bk] = h; Bs_lo[bn + j][bk] = l;
            }
        }
        __syncthreads();

#pragma unroll
        for (int kk = 0; kk < BK; kk += 16) {
            unsigned ahi[2][4], alo[2][4];
            const int c = kk + 2 * qc;
#pragma unroll
            for (int mt = 0; mt < 2; mt++) {
                int r = wm * 32 + mt * 16 + qr;
                ahi[mt][0] = *(const unsigned*)&As_hi[r][c];
                ahi[mt][1] = *(const unsigned*)&As_hi[r + 8][c];
                ahi[mt][2] = *(const unsigned*)&As_hi[r][c + 8];
                ahi[mt][3] = *(const unsigned*)&As_hi[r + 8][c + 8];
                alo[mt][0] = *(const unsigned*)&As_lo[r][c];
                alo[mt][1] = *(const unsigned*)&As_lo[r + 8][c];
                alo[mt][2] = *(const unsigned*)&As_lo[r][c + 8];
                alo[mt][3] = *(const unsigned*)&As_lo[r + 8][c + 8];
            }
#pragma unroll
            for (int nt = 0; nt < 4; nt++) {
                int nr = wn * 32 + nt * 8 + qr;
                unsigned bh[2], bl[2];
                bh[0] = *(const unsigned*)&Bs_hi[nr][c];
                bh[1] = *(const unsigned*)&Bs_hi[nr][c + 8];
                bl[0] = *(const unsigned*)&Bs_lo[nr][c];
                bl[1] = *(const unsigned*)&Bs_lo[nr][c + 8];
#pragma unroll
                for (int mt = 0; mt < 2; mt++) {
                    mma_bf16(acc[mt][nt], ahi[mt], bh);
                    mma_bf16(acc[mt][nt], ahi[mt], bl);
                    mma_bf16(acc[mt][nt], alo[mt], bh);
                }
            }
        }
        __syncthreads();
    }

#pragma unroll
    for (int mt = 0; mt < 2; mt++)
#pragma unroll
        for (int nt = 0; nt < 4; nt++) {
            int R = wm * 32 + mt * 16 + qr;
            int C = wn * 32 + nt * 8 + 2 * qc;
#pragma unroll
            for (int half = 0; half < 2; half++) {
                int r = R + half * 8;
                float2 o;
                o.x = acc[mt][nt][2 * half];
                o.y = acc[mt][nt][2 * half + 1];
                *(float2*)&g_orow[(rowbase + r) * (size_t)DDIM + n0 + C] = o;
            }
        }
}

// ============================ combine ===================================
__global__ void k_combine(float* __restrict__ out) {
    int idx = blockIdx.x * blockDim.x + threadIdx.x;
    if (idx >= TOK * DDIM) return;
    int t = idx >> 10;
    int d = idx & (DDIM - 1);
    float sh = g_orow[((size_t)ROWCAP + t) * DDIM + d];
    int   r0 = g_rowof[2 * t], r1 = g_rowof[2 * t + 1];
    float v = 0.0625f * sh
            + 0.5f * (g_gw[2 * t] * g_orow[(size_t)r0 * DDIM + d]
                    + g_gw[2 * t + 1] * g_orow[(size_t)r1 * DDIM + d]);
    out[idx] = v;
}

// ============================ launch ====================================
extern "C" void kernel_launch(void* const* d_in, const int* in_sizes, int n_in,
                              void* d_out, int out_size) {
    const float* x   = (const float*)d_in[0];
    const float* gW  = (const float*)d_in[1];
    const float* w1e = (const float*)d_in[2];
    const float* w3e = (const float*)d_in[3];
    const float* w2e = (const float*)d_in[4];
    const float* w1s = (const float*)d_in[5];
    const float* w3s = (const float*)d_in[6];
    const float* w2s = (const float*)d_in[7];
    float* out = (float*)d_out;

    k_reset<<<1, 32>>>();
    k_gate<<<TOK / 8, 256>>>(x, gW);

    dim3 g1(FDIM / BN, TOK / BM, NEXP + 1);
    k_gemm1<<<g1, 256>>>(x, w1e, w3e, w1s, w3s);

    dim3 g2(DDIM / BN, TOK / BM, NEXP + 1);
    k_gemm2<<<g2, 256>>>(w2e, w2s);

    k_combine<<<(TOK * DDIM) / 256, 256>>>(out);
}

// round 4
// speedup vs baseline: 3.0918x; 1.4098x over previous
#include <cuda_runtime.h>
#include <cuda_bf16.h>
#include <math.h>
#include <cstdint>
#include <string.h>

// ---------------- problem constants ----------------
#define TOK   2048
#define DDIM  1024
#define FDIM  4096
#define NEXP  8
#define FSH   512
#define TOPK  2
#define ROWCAP (NEXP*TOK)
#define NROWS  (ROWCAP + TOK)
#define NSLOT  9          // 8 routed + merged shared (slot 8)

// ---------------- scratch (device globals) ----------------
__device__ int   g_cnt[NEXP];
__device__ int   g_tok[ROWCAP];
__device__ int   g_rowof[TOK * TOPK];
__device__ float g_gw[TOK * TOPK];
__device__ __nv_bfloat16 g_x_hi[TOK * DDIM], g_x_lo[TOK * DDIM];
__device__ __nv_bfloat16 g_w1T_hi[(size_t)NSLOT * FDIM * DDIM];
__device__ __nv_bfloat16 g_w1T_lo[(size_t)NSLOT * FDIM * DDIM];
__device__ __nv_bfloat16 g_w3T_hi[(size_t)NSLOT * FDIM * DDIM];
__device__ __nv_bfloat16 g_w3T_lo[(size_t)NSLOT * FDIM * DDIM];
__device__ __nv_bfloat16 g_w2T_hi[(size_t)NSLOT * DDIM * FDIM];
__device__ __nv_bfloat16 g_w2T_lo[(size_t)NSLOT * DDIM * FDIM];
__device__ __nv_bfloat16 g_h_hi[(size_t)NROWS * FDIM];
__device__ __nv_bfloat16 g_h_lo[(size_t)NROWS * FDIM];
__device__ float g_orow[(size_t)NROWS * DDIM];

// ---------------- helpers ----------------
__device__ __forceinline__ uint32_t smem_u32(const void* p) {
    uint32_t a;
    asm("{ .reg .u64 t; cvta.to.shared.u64 t, %1; cvt.u32.u64 %0, t; }" : "=r"(a) : "l"(p));
    return a;
}
__device__ __forceinline__ void ldsm4(uint32_t* r, uint32_t a) {
    asm volatile("ldmatrix.sync.aligned.m8n8.x4.shared.b16 {%0,%1,%2,%3}, [%4];"
                 : "=r"(r[0]), "=r"(r[1]), "=r"(r[2]), "=r"(r[3]) : "r"(a));
}
__device__ __forceinline__ void mma_bf16(float* c, const uint32_t* a, const uint32_t* b) {
    asm volatile(
        "mma.sync.aligned.m16n8k16.row.col.f32.bf16.bf16.f32 "
        "{%0,%1,%2,%3},{%4,%5,%6,%7},{%8,%9},{%0,%1,%2,%3};"
        : "+f"(c[0]), "+f"(c[1]), "+f"(c[2]), "+f"(c[3])
        : "r"(a[0]), "r"(a[1]), "r"(a[2]), "r"(a[3]), "r"(b[0]), "r"(b[1]));
}
#define CP16(dst, src) \
    asm volatile("cp.async.cg.shared.global [%0], [%1], 16;" :: "r"(dst), "l"(src))
#define CPCOMMIT() asm volatile("cp.async.commit_group;" ::: "memory")
#define CPWAIT1()  asm volatile("cp.async.wait_group 1;" ::: "memory")
#define CPWAIT0()  asm volatile("cp.async.wait_group 0;" ::: "memory")

__device__ __forceinline__ void split_bf16(float v, __nv_bfloat16& h, __nv_bfloat16& l) {
    h = __float2bfloat16(v);
    l = __float2bfloat16(v - __bfloat162float(h));
}
__device__ __forceinline__ unsigned pk2(__nv_bfloat16 a, __nv_bfloat16 b) {
    __nv_bfloat162 t = __halves2bfloat162(a, b);
    unsigned r; memcpy(&r, &t, 4); return r;
}

// ============================ reset / gate ===============================
__global__ void k_reset() {
    if (threadIdx.x < NEXP) g_cnt[threadIdx.x] = 0;
}

__global__ void k_gate(const float* __restrict__ x, const float* __restrict__ gateW) {
    int gwarp = (blockIdx.x * blockDim.x + threadIdx.x) >> 5;
    int lane  = threadIdx.x & 31;
    if (gwarp >= TOK) return;
    const float* xr = x + (size_t)gwarp * DDIM;
    float xv[32];
#pragma unroll
    for (int i = 0; i < 32; i++) xv[i] = xr[lane + 32 * i];
    float logit[NEXP];
#pragma unroll
    for (int e = 0; e < NEXP; e++) {
        const float* wr = gateW + e * DDIM;
        float acc = 0.f;
#pragma unroll
        for (int i = 0; i < 32; i++) acc += xv[i] * wr[lane + 32 * i];
#pragma unroll
        for (int o = 16; o > 0; o >>= 1) acc += __shfl_xor_sync(0xffffffffu, acc, o);
        logit[e] = acc;
    }
    if (lane == 0) {
        float m = logit[0];
#pragma unroll
        for (int e = 1; e < NEXP; e++) m = fmaxf(m, logit[e]);
        float p[NEXP], den = 0.f;
#pragma unroll
        for (int e = 0; e < NEXP; e++) { p[e] = expf(logit[e] - m); den += p[e]; }
        int i1 = 0;
#pragma unroll
        for (int e = 1; e < NEXP; e++) if (p[e] > p[i1]) i1 = e;
        int i2 = (i1 == 0) ? 1 : 0;
#pragma unroll
        for (int e = 0; e < NEXP; e++) if (e != i2 && e != i1 && p[e] > p[i2]) i2 = e;
        int pos1 = atomicAdd(&g_cnt[i1], 1);
        int r1 = i1 * TOK + pos1;
        g_tok[r1] = gwarp;
        g_rowof[2 * gwarp + 0] = r1;
        g_gw[2 * gwarp + 0] = p[i1] / den;
        int pos2 = atomicAdd(&g_cnt[i2], 1);
        int r2 = i2 * TOK + pos2;
        g_tok[r2] = gwarp;
        g_rowof[2 * gwarp + 1] = r2;
        g_gw[2 * gwarp + 1] = p[i2] / den;
    }
}

// ===================== weight transpose + split ==========================
__global__ __launch_bounds__(256) void k_transplit(
    const float* __restrict__ src, int dst_id, size_t extra,
    int R, int C, size_t sstride, size_t dstride)
{
    __shared__ float tile[32][33];
    __nv_bfloat16 *dhi, *dlo;
    if      (dst_id == 0) { dhi = g_w1T_hi; dlo = g_w1T_lo; }
    else if (dst_id == 1) { dhi = g_w3T_hi; dlo = g_w3T_lo; }
    else                  { dhi = g_w2T_hi; dlo = g_w2T_lo; }
    dhi += extra; dlo += extra;

    int z = blockIdx.z;
    const float* s = src + (size_t)z * sstride;
    size_t dbase = (size_t)z * dstride;
    int c0 = blockIdx.x * 32, r0 = blockIdx.y * 32;
    int tx = threadIdx.x & 31, ty = threadIdx.x >> 5;
#pragma unroll
    for (int i = 0; i < 4; i++)
        tile[ty + 8 * i][tx] = s[(size_t)(r0 + ty + 8 * i) * C + c0 + tx];
    __syncthreads();
#pragma unroll
    for (int i = 0; i < 4; i++) {
        float v = tile[tx][ty + 8 * i];
        __nv_bfloat16 h, l; split_bf16(v, h, l);
        size_t o = dbase + (size_t)(c0 + ty + 8 * i) * R + r0 + tx;
        dhi[o] = h; dlo[o] = l;
    }
}

__global__ void k_xsplit(const float* __restrict__ x) {
    int i = blockIdx.x * blockDim.x + threadIdx.x;
    float v = x[i];
    __nv_bfloat16 h, l; split_bf16(v, h, l);
    g_x_hi[i] = h; g_x_lo[i] = l;
}

// ============================ GEMM tiles ================================
// BM=128, BN=64, BK=32, 8 warps (wm=w>>1 covers 32 M-rows, wn=w&1 covers 32 N-cols)
#define LDT 40          // smem row stride in bf16 elems (80B, conflict-free ldmatrix)

// ---- GEMM1 smem layout (elem offsets within one stage) ----
#define G1_AH   0
#define G1_AL   5120
#define G1_BGH  10240
#define G1_BGL  12800
#define G1_BUH  15360
#define G1_BUL  17920
#define G1_STG  20480                 // elems / stage
#define G1_STGB (G1_STG * 2)          // bytes / stage
#define G1_SMEM (2 * G1_STGB + 512)   // + stok

__global__ __launch_bounds__(256) void k_gemm1() {
    const int z  = blockIdx.z;
    const int m0 = blockIdx.y * 128;
    const int n0 = blockIdx.x * 64;
    const int M  = (z < NEXP) ? g_cnt[z] : TOK;
    if (m0 >= M) return;
    const size_t rowbase = (z < NEXP) ? ((size_t)z * TOK + m0) : ((size_t)ROWCAP + m0);

    extern __shared__ __align__(16) char sm[];
    int* stok = (int*)(sm + 2 * G1_STGB);
    const int tid = threadIdx.x;
    if (tid < 128) {
        int r = m0 + tid; if (r > M - 1) r = M - 1;
        stok[tid] = (z < NEXP) ? g_tok[z * TOK + r] : r;
    }
    __syncthreads();

    const uint32_t sbu = smem_u32(sm);
    const int ra = tid >> 2, c4 = tid & 3;
    const int tA0 = stok[ra], tA1 = stok[64 + ra];
    const __nv_bfloat16* sxh0 = g_x_hi + (size_t)tA0 * DDIM + c4 * 8;
    const __nv_bfloat16* sxh1 = g_x_hi + (size_t)tA1 * DDIM + c4 * 8;
    const __nv_bfloat16* sxl0 = g_x_lo + (size_t)tA0 * DDIM + c4 * 8;
    const __nv_bfloat16* sxl1 = g_x_lo + (size_t)tA1 * DDIM + c4 * 8;
    const size_t bsrc = ((size_t)z * FDIM + n0 + ra) * DDIM + c4 * 8;
    const __nv_bfloat16 *s1h = g_w1T_hi + bsrc, *s1l = g_w1T_lo + bsrc;
    const __nv_bfloat16 *s3h = g_w3T_hi + bsrc, *s3l = g_w3T_lo + bsrc;

    const uint32_t dA0 = (G1_AH + ra * LDT + c4 * 8) * 2;
    const uint32_t dA1 = dA0 + 64 * LDT * 2;
    const uint32_t dL0 = dA0 + (G1_AL - G1_AH) * 2;
    const uint32_t dL1 = dL0 + 64 * LDT * 2;
    const uint32_t dB  = (ra * LDT + c4 * 8) * 2;

    const int lane = tid & 31, w = tid >> 5;
    const int wm = w >> 1, wn = w & 1;
    const int qr = lane >> 2, qc = lane & 3;
    const uint32_t aoff = ((wm * 32 + (lane & 15)) * LDT + (lane >> 4) * 8) * 2;
    const uint32_t boff = ((wn * 32 + (lane & 7) + ((lane >> 4) & 1) * 8) * LDT
                           + ((lane >> 3) & 1) * 8) * 2;

    float accg[2][4][4] = {}, accu[2][4][4] = {};

#define G1_LOAD(it, s) do { \
    const int k0 = (it) * 32; \
    const uint32_t db = sbu + (s) * G1_STGB; \
    CP16(db + dA0, sxh0 + k0); \
    CP16(db + dA1, sxh1 + k0); \
    CP16(db + dL0, sxl0 + k0); \
    CP16(db + dL1, sxl1 + k0); \
    CP16(db + G1_BGH * 2 + dB, s1h + k0); \
    CP16(db + G1_BGL * 2 + dB, s1l + k0); \
    CP16(db + G1_BUH * 2 + dB, s3h + k0); \
    CP16(db + G1_BUL * 2 + dB, s3l + k0); \
    CPCOMMIT(); \
} while (0)

    G1_LOAD(0, 0);

    const int NIT = DDIM / 32;
    for (int it = 0; it < NIT; it++) {
        if (it + 1 < NIT) { G1_LOAD(it + 1, (it + 1) & 1); CPWAIT1(); }
        else              { CPWAIT0(); }
        __syncthreads();
        const uint32_t stg = sbu + (it & 1) * G1_STGB;
#pragma unroll
        for (int ks = 0; ks < 32; ks += 16) {
            uint32_t ah[2][4], al[2][4];
#pragma unroll
            for (int mt = 0; mt < 2; mt++) {
                ldsm4(ah[mt], stg + aoff + mt * (16 * LDT * 2) + ks * 2);
                ldsm4(al[mt], stg + (G1_AL * 2) + aoff + mt * (16 * LDT * 2) + ks * 2);
            }
#pragma unroll
            for (int nh = 0; nh < 2; nh++) {
                const uint32_t bo = boff + nh * (16 * LDT * 2) + ks * 2;
                uint32_t bgh[4], bgl[4], buh[4], bul[4];
                ldsm4(bgh, stg + G1_BGH * 2 + bo);
                ldsm4(bgl, stg + G1_BGL * 2 + bo);
                ldsm4(buh, stg + G1_BUH * 2 + bo);
                ldsm4(bul, stg + G1_BUL * 2 + bo);
#pragma unroll
                for (int t = 0; t < 2; t++) {
                    const int nt = nh * 2 + t;
#pragma unroll
                    for (int mt = 0; mt < 2; mt++) {
                        mma_bf16(accg[mt][nt], ah[mt], bgh + 2 * t);
                        mma_bf16(accg[mt][nt], ah[mt], bgl + 2 * t);
                        mma_bf16(accg[mt][nt], al[mt], bgh + 2 * t);
                        mma_bf16(accu[mt][nt], ah[mt], buh + 2 * t);
                        mma_bf16(accu[mt][nt], ah[mt], bul + 2 * t);
                        mma_bf16(accu[mt][nt], al[mt], buh + 2 * t);
                    }
                }
            }
        }
        __syncthreads();
    }
#undef G1_LOAD

    // epilogue: silu(g)*u -> bf16 hi/lo
#pragma unroll
    for (int mt = 0; mt < 2; mt++)
#pragma unroll
        for (int nt = 0; nt < 4; nt++) {
            const int R = wm * 32 + mt * 16 + qr;
            const int C = wn * 32 + nt * 8 + 2 * qc;
#pragma unroll
            for (int half = 0; half < 2; half++) {
                const int r = R + half * 8;
                float g0 = accg[mt][nt][2 * half],     u0 = accu[mt][nt][2 * half];
                float g1 = accg[mt][nt][2 * half + 1], u1 = accu[mt][nt][2 * half + 1];
                float o0 = g0 / (1.f + __expf(-g0)) * u0;
                float o1 = g1 / (1.f + __expf(-g1)) * u1;
                __nv_bfloat16 h0, l0, h1, l1;
                split_bf16(o0, h0, l0); split_bf16(o1, h1, l1);
                const size_t idx = (rowbase + r) * (size_t)FDIM + n0 + C;
                *(unsigned*)&g_h_hi[idx] = pk2(h0, h1);
                *(unsigned*)&g_h_lo[idx] = pk2(l0, l1);
            }
        }
}

// ---- GEMM2 smem layout ----
#define G2_AH   0
#define G2_AL   5120
#define G2_BH   10240
#define G2_BL   12800
#define G2_STG  15360
#define G2_STGB (G2_STG * 2)
#define G2_SMEM (2 * G2_STGB)

__global__ __launch_bounds__(256) void k_gemm2() {
    const int z  = blockIdx.z;
    const int m0 = blockIdx.y * 128;
    const int n0 = blockIdx.x * 64;
    const int M  = (z < NEXP) ? g_cnt[z] : TOK;
    if (m0 >= M) return;
    const size_t rowbase = (z < NEXP) ? ((size_t)z * TOK + m0) : ((size_t)ROWCAP + m0);

    extern __shared__ __align__(16) char sm[];
    const uint32_t sbu = smem_u32(sm);
    const int tid = threadIdx.x;
    const int ra = tid >> 2, c4 = tid & 3;

    const __nv_bfloat16* sah0 = g_h_hi + (rowbase + ra) * (size_t)FDIM + c4 * 8;
    const __nv_bfloat16* sah1 = g_h_hi + (rowbase + 64 + ra) * (size_t)FDIM + c4 * 8;
    const __nv_bfloat16* sal0 = g_h_lo + (rowbase + ra) * (size_t)FDIM + c4 * 8;
    const __nv_bfloat16* sal1 = g_h_lo + (rowbase + 64 + ra) * (size_t)FDIM + c4 * 8;
    const size_t bsrc = ((size_t)z * DDIM + n0 + ra) * FDIM + c4 * 8;
    const __nv_bfloat16 *sbh = g_w2T_hi + bsrc, *sbl = g_w2T_lo + bsrc;

    const uint32_t dA0 = (G2_AH + ra * LDT + c4 * 8) * 2;
    const uint32_t dA1 = dA0 + 64 * LDT * 2;
    const uint32_t dL0 = dA0 + (G2_AL - G2_AH) * 2;
    const uint32_t dL1 = dL0 + 64 * LDT * 2;
    const uint32_t dB  = (ra * LDT + c4 * 8) * 2;

    const int lane = tid & 31, w = tid >> 5;
    const int wm = w >> 1, wn = w & 1;
    const int qr = lane >> 2, qc = lane & 3;
    const uint32_t aoff = ((wm * 32 + (lane & 15)) * LDT + (lane >> 4) * 8) * 2;
    const uint32_t boff = ((wn * 32 + (lane & 7) + ((lane >> 4) & 1) * 8) * LDT
                           + ((lane >> 3) & 1) * 8) * 2;

    float acc[2][4][4] = {};

#define G2_LOAD(it, s) do { \
    const int k0 = (it) * 32; \
    const uint32_t db = sbu + (s) * G2_STGB; \
    CP16(db + dA0, sah0 + k0); \
    CP16(db + dA1, sah1 + k0); \
    CP16(db + dL0, sal0 + k0); \
    CP16(db + dL1, sal1 + k0); \
    CP16(db + G2_BH * 2 + dB, sbh + k0); \
    CP16(db + G2_BL * 2 + dB, sbl + k0); \
    CPCOMMIT(); \
} while (0)

    G2_LOAD(0, 0);

    const int NIT = FDIM / 32;
    for (int it = 0; it < NIT; it++) {
        if (it + 1 < NIT) { G2_LOAD(it + 1, (it + 1) & 1); CPWAIT1(); }
        else              { CPWAIT0(); }
        __syncthreads();
        const uint32_t stg = sbu + (it & 1) * G2_STGB;
#pragma unroll
        for (int ks = 0; ks < 32; ks += 16) {
            uint32_t ah[2][4], al[2][4];
#pragma unroll
            for (int mt = 0; mt < 2; mt++) {
                ldsm4(ah[mt], stg + aoff + mt * (16 * LDT * 2) + ks * 2);
                ldsm4(al[mt], stg + (G2_AL * 2) + aoff + mt * (16 * LDT * 2) + ks * 2);
            }
#pragma unroll
            for (int nh = 0; nh < 2; nh++) {
                const uint32_t bo = boff + nh * (16 * LDT * 2) + ks * 2;
                uint32_t bh[4], bl[4];
                ldsm4(bh, stg + G2_BH * 2 + bo);
                ldsm4(bl, stg + G2_BL * 2 + bo);
#pragma unroll
                for (int t = 0; t < 2; t++) {
                    const int nt = nh * 2 + t;
#pragma unroll
                    for (int mt = 0; mt < 2; mt++) {
                        mma_bf16(acc[mt][nt], ah[mt], bh + 2 * t);
                        mma_bf16(acc[mt][nt], ah[mt], bl + 2 * t);
                        mma_bf16(acc[mt][nt], al[mt], bh + 2 * t);
                    }
                }
            }
        }
        __syncthreads();
    }
#undef G2_LOAD

#pragma unroll
    for (int mt = 0; mt < 2; mt++)
#pragma unroll
        for (int nt = 0; nt < 4; nt++) {
            const int R = wm * 32 + mt * 16 + qr;
            const int C = wn * 32 + nt * 8 + 2 * qc;
#pragma unroll
            for (int half = 0; half < 2; half++) {
                const int r = R + half * 8;
                float2 o;
                o.x = acc[mt][nt][2 * half];
                o.y = acc[mt][nt][2 * half + 1];
                *(float2*)&g_orow[(rowbase + r) * (size_t)DDIM + n0 + C] = o;
            }
        }
}

// ============================ combine ===================================
__global__ void k_combine(float* __restrict__ out) {
    int idx = blockIdx.x * blockDim.x + threadIdx.x;
    if (idx >= TOK * DDIM) return;
    int t = idx >> 10;
    int d = idx & (DDIM - 1);
    float sh = g_orow[((size_t)ROWCAP + t) * DDIM + d];
    int   r0 = g_rowof[2 * t], r1 = g_rowof[2 * t + 1];
    float v = 0.0625f * sh
            + 0.5f * (g_gw[2 * t] * g_orow[(size_t)r0 * DDIM + d]
                    + g_gw[2 * t + 1] * g_orow[(size_t)r1 * DDIM + d]);
    out[idx] = v;
}

// ============================ launch ====================================
extern "C" void kernel_launch(void* const* d_in, const int* in_sizes, int n_in,
                              void* d_out, int out_size) {
    const float* x   = (const float*)d_in[0];
    const float* gW  = (const float*)d_in[1];
    const float* w1e = (const float*)d_in[2];
    const float* w3e = (const float*)d_in[3];
    const float* w2e = (const float*)d_in[4];
    const float* w1s = (const float*)d_in[5];
    const float* w3s = (const float*)d_in[6];
    const float* w2s = (const float*)d_in[7];
    float* out = (float*)d_out;

    cudaFuncSetAttribute(k_gemm1, cudaFuncAttributeMaxDynamicSharedMemorySize, G1_SMEM);
    cudaFuncSetAttribute(k_gemm2, cudaFuncAttributeMaxDynamicSharedMemorySize, G2_SMEM);

    k_reset<<<1, 32>>>();
    k_gate<<<TOK / 8, 256>>>(x, gW);
    k_xsplit<<<TOK * DDIM / 256, 256>>>(x);

    // routed weights: [D,F] -> [F,D] (w1,w3) and [F,D] -> [D,F] (w2)
    k_transplit<<<dim3(FDIM / 32, DDIM / 32, NEXP), 256>>>(
        w1e, 0, 0, DDIM, FDIM, (size_t)DDIM * FDIM, (size_t)FDIM * DDIM);
    k_transplit<<<dim3(FDIM / 32, DDIM / 32, NEXP), 256>>>(
        w3e, 1, 0, DDIM, FDIM, (size_t)DDIM * FDIM, (size_t)FDIM * DDIM);
    k_transplit<<<dim3(DDIM / 32, FDIM / 32, NEXP), 256>>>(
        w2e, 2, 0, FDIM, DDIM, (size_t)FDIM * DDIM, (size_t)DDIM * FDIM);
    // shared weights -> slot 8 (block-concatenated)
    k_transplit<<<dim3(FSH / 32, DDIM / 32, NEXP), 256>>>(
        w1s, 0, (size_t)NEXP * FDIM * DDIM, DDIM, FSH, (size_t)DDIM * FSH, (size_t)FSH * DDIM);
    k_transplit<<<dim3(FSH / 32, DDIM / 32, NEXP), 256>>>(
        w3s, 1, (size_t)NEXP * FDIM * DDIM, DDIM, FSH, (size_t)DDIM * FSH, (size_t)FSH * DDIM);
    k_transplit<<<dim3(DDIM / 32, FDIM / 32, 1), 256>>>(
        w2s, 2, (size_t)NEXP * DDIM * FDIM, FDIM, DDIM, 0, 0);

    k_gemm1<<<dim3(FDIM / 64, TOK / 128, NSLOT), 256, G1_SMEM>>>();
    k_gemm2<<<dim3(DDIM / 64, TOK / 128, NSLOT), 256, G2_SMEM>>>();
    k_combine<<<(TOK * DDIM) / 256, 256>>>(out);
}

// round 5
// speedup vs baseline: 4.4531x; 1.4403x over previous
#include <cuda_runtime.h>
#include <cuda_fp16.h>
#include <math.h>
#include <cstdint>
#include <string.h>

// ---------------- problem constants ----------------
#define TOK   2048
#define DDIM  1024
#define FDIM  4096
#define NEXP  8
#define FSH   512
#define TOPK  2
#define ROWCAP (NEXP*TOK)
#define NROWS  (ROWCAP + TOK)
#define NSLOT  9          // 8 routed + merged shared (slot 8)

// ---------------- scratch (device globals) ----------------
__device__ int   g_cnt[NEXP];
__device__ int   g_tok[ROWCAP];
__device__ int   g_rowof[TOK * TOPK];
__device__ float g_gw[TOK * TOPK];
__device__ __half g_x_hi[TOK * DDIM], g_x_lo[TOK * DDIM];
__device__ __half g_w1T[(size_t)NSLOT * FDIM * DDIM];   // [slot][F][D] fp16
__device__ __half g_w3T[(size_t)NSLOT * FDIM * DDIM];
__device__ __half g_w2T[(size_t)NSLOT * DDIM * FDIM];   // [slot][D][F] fp16
__device__ __half g_h_hi[(size_t)NROWS * FDIM];
__device__ __half g_h_lo[(size_t)NROWS * FDIM];
__device__ float g_orow[(size_t)NROWS * DDIM];

// ---------------- helpers ----------------
__device__ __forceinline__ uint32_t smem_u32(const void* p) {
    uint32_t a;
    asm("{ .reg .u64 t; cvta.to.shared.u64 t, %1; cvt.u32.u64 %0, t; }" : "=r"(a) : "l"(p));
    return a;
}
__device__ __forceinline__ void ldsm4(uint32_t* r, uint32_t a) {
    asm volatile("ldmatrix.sync.aligned.m8n8.x4.shared.b16 {%0,%1,%2,%3}, [%4];"
                 : "=r"(r[0]), "=r"(r[1]), "=r"(r[2]), "=r"(r[3]) : "r"(a));
}
__device__ __forceinline__ void mma_f16(float* c, const uint32_t* a, const uint32_t* b) {
    asm volatile(
        "mma.sync.aligned.m16n8k16.row.col.f32.f16.f16.f32 "
        "{%0,%1,%2,%3},{%4,%5,%6,%7},{%8,%9},{%0,%1,%2,%3};"
        : "+f"(c[0]), "+f"(c[1]), "+f"(c[2]), "+f"(c[3])
        : "r"(a[0]), "r"(a[1]), "r"(a[2]), "r"(a[3]), "r"(b[0]), "r"(b[1]));
}
#define CP16(dst, src) \
    asm volatile("cp.async.cg.shared.global [%0], [%1], 16;" :: "r"(dst), "l"(src))
#define CPCOMMIT() asm volatile("cp.async.commit_group;" ::: "memory")
#define CPWAIT1()  asm volatile("cp.async.wait_group 1;" ::: "memory")

__device__ __forceinline__ void split_h(float v, __half& h, __half& l) {
    h = __float2half_rn(v);
    l = __float2half_rn(v - __half2float(h));
}
__device__ __forceinline__ unsigned pk2h(__half a, __half b) {
    __half2 t = __halves2half2(a, b);
    unsigned r; memcpy(&r, &t, 4); return r;
}

// ============================ reset / gate ===============================
__global__ void k_reset() {
    if (threadIdx.x < NEXP) g_cnt[threadIdx.x] = 0;
}

__global__ void k_gate(const float* __restrict__ x, const float* __restrict__ gateW) {
    int gwarp = (blockIdx.x * blockDim.x + threadIdx.x) >> 5;
    int lane  = threadIdx.x & 31;
    if (gwarp >= TOK) return;
    const float* xr = x + (size_t)gwarp * DDIM;
    float xv[32];
#pragma unroll
    for (int i = 0; i < 32; i++) xv[i] = xr[lane + 32 * i];
    float logit[NEXP];
#pragma unroll
    for (int e = 0; e < NEXP; e++) {
        const float* wr = gateW + e * DDIM;
        float acc = 0.f;
#pragma unroll
        for (int i = 0; i < 32; i++) acc += xv[i] * wr[lane + 32 * i];
#pragma unroll
        for (int o = 16; o > 0; o >>= 1) acc += __shfl_xor_sync(0xffffffffu, acc, o);
        logit[e] = acc;
    }
    if (lane == 0) {
        float m = logit[0];
#pragma unroll
        for (int e = 1; e < NEXP; e++) m = fmaxf(m, logit[e]);
        float p[NEXP], den = 0.f;
#pragma unroll
        for (int e = 0; e < NEXP; e++) { p[e] = expf(logit[e] - m); den += p[e]; }
        int i1 = 0;
#pragma unroll
        for (int e = 1; e < NEXP; e++) if (p[e] > p[i1]) i1 = e;
        int i2 = (i1 == 0) ? 1 : 0;
#pragma unroll
        for (int e = 0; e < NEXP; e++) if (e != i2 && e != i1 && p[e] > p[i2]) i2 = e;
        int pos1 = atomicAdd(&g_cnt[i1], 1);
        int r1 = i1 * TOK + pos1;
        g_tok[r1] = gwarp;
        g_rowof[2 * gwarp + 0] = r1;
        g_gw[2 * gwarp + 0] = p[i1] / den;
        int pos2 = atomicAdd(&g_cnt[i2], 1);
        int r2 = i2 * TOK + pos2;
        g_tok[r2] = gwarp;
        g_rowof[2 * gwarp + 1] = r2;
        g_gw[2 * gwarp + 1] = p[i2] / den;
    }
}

// ===================== weight transpose (fp16, single) ===================
// src: z-th block [R][C] fp32 -> dst: z-th block [C][R] fp16
__global__ __launch_bounds__(256) void k_transplit(
    const float* __restrict__ src, int dst_id, size_t extra,
    int R, int C, size_t sstride, size_t dstride)
{
    __shared__ float tile[32][33];
    __half* dst;
    if      (dst_id == 0) dst = g_w1T;
    else if (dst_id == 1) dst = g_w3T;
    else                  dst = g_w2T;
    dst += extra;

    int z = blockIdx.z;
    const float* s = src + (size_t)z * sstride;
    size_t dbase = (size_t)z * dstride;
    int c0 = blockIdx.x * 32, r0 = blockIdx.y * 32;
    int tx = threadIdx.x & 31, ty = threadIdx.x >> 5;
#pragma unroll
    for (int i = 0; i < 4; i++)
        tile[ty + 8 * i][tx] = s[(size_t)(r0 + ty + 8 * i) * C + c0 + tx];
    __syncthreads();
#pragma unroll
    for (int i = 0; i < 4; i++) {
        float v = tile[tx][ty + 8 * i];
        size_t o = dbase + (size_t)(c0 + ty + 8 * i) * R + r0 + tx;
        dst[o] = __float2half_rn(v);
    }
}

__global__ void k_xsplit(const float* __restrict__ x) {
    int i = blockIdx.x * blockDim.x + threadIdx.x;
    float v = x[i];
    __half h, l; split_h(v, h, l);
    g_x_hi[i] = h; g_x_lo[i] = l;
}

// ============================ GEMM tiles ================================
// BM=128, BN=64, BK=32, 8 warps (wm covers 32 M-rows, wn covers 32 N-cols)
#define LDT 40          // smem row stride in fp16 elems (80B, conflict-free ldmatrix)
#define NSTG 3

// ---- GEMM1 smem layout (elem offsets within one stage) ----
#define G1_AH   0
#define G1_AL   5120
#define G1_BG   10240
#define G1_BU   12800
#define G1_STG  15360                 // elems / stage
#define G1_STGB (G1_STG * 2)          // bytes / stage
#define G1_SMEM (NSTG * G1_STGB + 512)

__global__ __launch_bounds__(256) void k_gemm1() {
    const int z  = blockIdx.z;
    const int m0 = blockIdx.y * 128;
    const int n0 = blockIdx.x * 64;
    const int M  = (z < NEXP) ? g_cnt[z] : TOK;
    if (m0 >= M) return;
    const size_t rowbase = (z < NEXP) ? ((size_t)z * TOK + m0) : ((size_t)ROWCAP + m0);

    extern __shared__ __align__(16) char sm[];
    int* stok = (int*)(sm + NSTG * G1_STGB);
    const int tid = threadIdx.x;
    if (tid < 128) {
        int r = m0 + tid; if (r > M - 1) r = M - 1;
        stok[tid] = (z < NEXP) ? g_tok[z * TOK + r] : r;
    }
    __syncthreads();

    const uint32_t sbu = smem_u32(sm);
    const int ra = tid >> 2, c4 = tid & 3;
    const int tA0 = stok[ra], tA1 = stok[64 + ra];
    const __half* sxh0 = g_x_hi + (size_t)tA0 * DDIM + c4 * 8;
    const __half* sxh1 = g_x_hi + (size_t)tA1 * DDIM + c4 * 8;
    const __half* sxl0 = g_x_lo + (size_t)tA0 * DDIM + c4 * 8;
    const __half* sxl1 = g_x_lo + (size_t)tA1 * DDIM + c4 * 8;
    const size_t bsrc = ((size_t)z * FDIM + n0 + ra) * DDIM + c4 * 8;
    const __half *s1 = g_w1T + bsrc, *s3 = g_w3T + bsrc;

    const uint32_t dA0 = (G1_AH + ra * LDT + c4 * 8) * 2;
    const uint32_t dA1 = dA0 + 64 * LDT * 2;
    const uint32_t dL0 = dA0 + (G1_AL - G1_AH) * 2;
    const uint32_t dL1 = dL0 + 64 * LDT * 2;
    const uint32_t dB  = (ra * LDT + c4 * 8) * 2;

    const int lane = tid & 31, w = tid >> 5;
    const int wm = w >> 1, wn = w & 1;
    const int qr = lane >> 2, qc = lane & 3;
    const uint32_t aoff = ((wm * 32 + (lane & 15)) * LDT + (lane >> 4) * 8) * 2;
    const uint32_t boff = ((wn * 32 + (lane & 7) + ((lane >> 4) & 1) * 8) * LDT
                           + ((lane >> 3) & 1) * 8) * 2;

    float accg[2][4][4] = {}, accu[2][4][4] = {};

#define G1_LOAD(it) do { \
    const int k0 = (it) * 32; \
    const uint32_t db = sbu + ((it) % NSTG) * G1_STGB; \
    CP16(db + dA0, sxh0 + k0); \
    CP16(db + dA1, sxh1 + k0); \
    CP16(db + dL0, sxl0 + k0); \
    CP16(db + dL1, sxl1 + k0); \
    CP16(db + G1_BG * 2 + dB, s1 + k0); \
    CP16(db + G1_BU * 2 + dB, s3 + k0); \
    CPCOMMIT(); \
} while (0)

    G1_LOAD(0);
    G1_LOAD(1);

    const int NIT = DDIM / 32;
    for (int it = 0; it < NIT; it++) {
        CPWAIT1();
        __syncthreads();
        if (it + 2 < NIT) G1_LOAD(it + 2); else CPCOMMIT();
        const uint32_t stg = sbu + (it % NSTG) * G1_STGB;
#pragma unroll
        for (int ks = 0; ks < 32; ks += 16) {
            uint32_t ah[2][4], al[2][4];
#pragma unroll
            for (int mt = 0; mt < 2; mt++) {
                ldsm4(ah[mt], stg + aoff + mt * (16 * LDT * 2) + ks * 2);
                ldsm4(al[mt], stg + (G1_AL * 2) + aoff + mt * (16 * LDT * 2) + ks * 2);
            }
#pragma unroll
            for (int nh = 0; nh < 2; nh++) {
                const uint32_t bo = boff + nh * (16 * LDT * 2) + ks * 2;
                uint32_t bg[4], bu[4];
                ldsm4(bg, stg + G1_BG * 2 + bo);
                ldsm4(bu, stg + G1_BU * 2 + bo);
#pragma unroll
                for (int t = 0; t < 2; t++) {
                    const int nt = nh * 2 + t;
#pragma unroll
                    for (int mt = 0; mt < 2; mt++) {
                        mma_f16(accg[mt][nt], ah[mt], bg + 2 * t);
                        mma_f16(accg[mt][nt], al[mt], bg + 2 * t);
                        mma_f16(accu[mt][nt], ah[mt], bu + 2 * t);
                        mma_f16(accu[mt][nt], al[mt], bu + 2 * t);
                    }
                }
            }
        }
    }
#undef G1_LOAD

    // epilogue: silu(g)*u -> fp16 hi/lo
#pragma unroll
    for (int mt = 0; mt < 2; mt++)
#pragma unroll
        for (int nt = 0; nt < 4; nt++) {
            const int R = wm * 32 + mt * 16 + qr;
            const int C = wn * 32 + nt * 8 + 2 * qc;
#pragma unroll
            for (int half = 0; half < 2; half++) {
                const int r = R + half * 8;
                float g0 = accg[mt][nt][2 * half],     u0 = accu[mt][nt][2 * half];
                float g1 = accg[mt][nt][2 * half + 1], u1 = accu[mt][nt][2 * half + 1];
                float o0 = g0 / (1.f + __expf(-g0)) * u0;
                float o1 = g1 / (1.f + __expf(-g1)) * u1;
                __half h0, l0, h1, l1;
                split_h(o0, h0, l0); split_h(o1, h1, l1);
                const size_t idx = (rowbase + r) * (size_t)FDIM + n0 + C;
                *(unsigned*)&g_h_hi[idx] = pk2h(h0, h1);
                *(unsigned*)&g_h_lo[idx] = pk2h(l0, l1);
            }
        }
}

// ---- GEMM2 smem layout ----
#define G2_AH   0
#define G2_AL   5120
#define G2_B    10240
#define G2_STG  12800
#define G2_STGB (G2_STG * 2)
#define G2_SMEM (NSTG * G2_STGB)

__global__ __launch_bounds__(256) void k_gemm2() {
    const int z  = blockIdx.z;
    const int m0 = blockIdx.y * 128;
    const int n0 = blockIdx.x * 64;
    const int M  = (z < NEXP) ? g_cnt[z] : TOK;
    if (m0 >= M) return;
    const size_t rowbase = (z < NEXP) ? ((size_t)z * TOK + m0) : ((size_t)ROWCAP + m0);

    extern __shared__ __align__(16) char sm[];
    const uint32_t sbu = smem_u32(sm);
    const int tid = threadIdx.x;
    const int ra = tid >> 2, c4 = tid & 3;

    const __half* sah0 = g_h_hi + (rowbase + ra) * (size_t)FDIM + c4 * 8;
    const __half* sah1 = g_h_hi + (rowbase + 64 + ra) * (size_t)FDIM + c4 * 8;
    const __half* sal0 = g_h_lo + (rowbase + ra) * (size_t)FDIM + c4 * 8;
    const __half* sal1 = g_h_lo + (rowbase + 64 + ra) * (size_t)FDIM + c4 * 8;
    const size_t bsrc = ((size_t)z * DDIM + n0 + ra) * FDIM + c4 * 8;
    const __half* sB = g_w2T + bsrc;

    const uint32_t dA0 = (G2_AH + ra * LDT + c4 * 8) * 2;
    const uint32_t dA1 = dA0 + 64 * LDT * 2;
    const uint32_t dL0 = dA0 + (G2_AL - G2_AH) * 2;
    const uint32_t dL1 = dL0 + 64 * LDT * 2;
    const uint32_t dB  = (ra * LDT + c4 * 8) * 2;

    const int lane = tid & 31, w = tid >> 5;
    const int wm = w >> 1, wn = w & 1;
    const int qr = lane >> 2, qc = lane & 3;
    const uint32_t aoff = ((wm * 32 + (lane & 15)) * LDT + (lane >> 4) * 8) * 2;
    const uint32_t boff = ((wn * 32 + (lane & 7) + ((lane >> 4) & 1) * 8) * LDT
                           + ((lane >> 3) & 1) * 8) * 2;

    float acc[2][4][4] = {};

#define G2_LOAD(it) do { \
    const int k0 = (it) * 32; \
    const uint32_t db = sbu + ((it) % NSTG) * G2_STGB; \
    CP16(db + dA0, sah0 + k0); \
    CP16(db + dA1, sah1 + k0); \
    CP16(db + dL0, sal0 + k0); \
    CP16(db + dL1, sal1 + k0); \
    CP16(db + G2_B * 2 + dB, sB + k0); \
    CPCOMMIT(); \
} while (0)

    G2_LOAD(0);
    G2_LOAD(1);

    const int NIT = FDIM / 32;
    for (int it = 0; it < NIT; it++) {
        CPWAIT1();
        __syncthreads();
        if (it + 2 < NIT) G2_LOAD(it + 2); else CPCOMMIT();
        const uint32_t stg = sbu + (it % NSTG) * G2_STGB;
#pragma unroll
        for (int ks = 0; ks < 32; ks += 16) {
            uint32_t ah[2][4], al[2][4];
#pragma unroll
            for (int mt = 0; mt < 2; mt++) {
                ldsm4(ah[mt], stg + aoff + mt * (16 * LDT * 2) + ks * 2);
                ldsm4(al[mt], stg + (G2_AL * 2) + aoff + mt * (16 * LDT * 2) + ks * 2);
            }
#pragma unroll
            for (int nh = 0; nh < 2; nh++) {
                const uint32_t bo = boff + nh * (16 * LDT * 2) + ks * 2;
                uint32_t bb[4];
                ldsm4(bb, stg + G2_B * 2 + bo);
#pragma unroll
                for (int t = 0; t < 2; t++) {
                    const int nt = nh * 2 + t;
#pragma unroll
                    for (int mt = 0; mt < 2; mt++) {
                        mma_f16(acc[mt][nt], ah[mt], bb + 2 * t);
                        mma_f16(acc[mt][nt], al[mt], bb + 2 * t);
                    }
                }
            }
        }
    }
#undef G2_LOAD

#pragma unroll
    for (int mt = 0; mt < 2; mt++)
#pragma unroll
        for (int nt = 0; nt < 4; nt++) {
            const int R = wm * 32 + mt * 16 + qr;
            const int C = wn * 32 + nt * 8 + 2 * qc;
#pragma unroll
            for (int half = 0; half < 2; half++) {
                const int r = R + half * 8;
                float2 o;
                o.x = acc[mt][nt][2 * half];
                o.y = acc[mt][nt][2 * half + 1];
                *(float2*)&g_orow[(rowbase + r) * (size_t)DDIM + n0 + C] = o;
            }
        }
}

// ============================ combine ===================================
__global__ void k_combine(float* __restrict__ out) {
    int idx = blockIdx.x * blockDim.x + threadIdx.x;
    if (idx >= TOK * DDIM) return;
    int t = idx >> 10;
    int d = idx & (DDIM - 1);
    float sh = g_orow[((size_t)ROWCAP + t) * DDIM + d];
    int   r0 = g_rowof[2 * t], r1 = g_rowof[2 * t + 1];
    float v = 0.0625f * sh
            + 0.5f * (g_gw[2 * t] * g_orow[(size_t)r0 * DDIM + d]
                    + g_gw[2 * t + 1] * g_orow[(size_t)r1 * DDIM + d]);
    out[idx] = v;
}

// ============================ launch ====================================
extern "C" void kernel_launch(void* const* d_in, const int* in_sizes, int n_in,
                              void* d_out, int out_size) {
    const float* x   = (const float*)d_in[0];
    const float* gW  = (const float*)d_in[1];
    const float* w1e = (const float*)d_in[2];
    const float* w3e = (const float*)d_in[3];
    const float* w2e = (const float*)d_in[4];
    const float* w1s = (const float*)d_in[5];
    const float* w3s = (const float*)d_in[6];
    const float* w2s = (const float*)d_in[7];
    float* out = (float*)d_out;

    cudaFuncSetAttribute(k_gemm1, cudaFuncAttributeMaxDynamicSharedMemorySize, G1_SMEM);
    cudaFuncSetAttribute(k_gemm2, cudaFuncAttributeMaxDynamicSharedMemorySize, G2_SMEM);

    k_reset<<<1, 32>>>();
    k_gate<<<TOK / 8, 256>>>(x, gW);
    k_xsplit<<<TOK * DDIM / 256, 256>>>(x);

    // routed weights: [D,F] -> [F,D] (w1,w3) and [F,D] -> [D,F] (w2)
    k_transplit<<<dim3(FDIM / 32, DDIM / 32, NEXP), 256>>>(
        w1e, 0, 0, DDIM, FDIM, (size_t)DDIM * FDIM, (size_t)FDIM * DDIM);
    k_transplit<<<dim3(FDIM / 32, DDIM / 32, NEXP), 256>>>(
        w3e, 1, 0, DDIM, FDIM, (size_t)DDIM * FDIM, (size_t)FDIM * DDIM);
    k_transplit<<<dim3(DDIM / 32, FDIM / 32, NEXP), 256>>>(
        w2e, 2, 0, FDIM, DDIM, (size_t)FDIM * DDIM, (size_t)DDIM * FDIM);
    // shared weights -> slot 8 (block-concatenated)
    k_transplit<<<dim3(FSH / 32, DDIM / 32, NEXP), 256>>>(
        w1s, 0, (size_t)NEXP * FDIM * DDIM, DDIM, FSH, (size_t)DDIM * FSH, (size_t)FSH * DDIM);
    k_transplit<<<dim3(FSH / 32, DDIM / 32, NEXP), 256>>>(
        w3s, 1, (size_t)NEXP * FDIM * DDIM, DDIM, FSH, (size_t)DDIM * FSH, (size_t)FSH * DDIM);
    k_transplit<<<dim3(DDIM / 32, FDIM / 32, 1), 256>>>(
        w2s, 2, (size_t)NEXP * DDIM * FDIM, FDIM, DDIM, 0, 0);

    k_gemm1<<<dim3(FDIM / 64, TOK / 128, NSLOT), 256, G1_SMEM>>>();
    k_gemm2<<<dim3(DDIM / 64, TOK / 128, NSLOT), 256, G2_SMEM>>>();
    k_combine<<<(TOK * DDIM) / 256, 256>>>(out);
}

// round 6
// speedup vs baseline: 4.6212x; 1.0377x over previous
#include <cuda_runtime.h>
#include <cuda_fp16.h>
#include <math.h>
#include <cstdint>
#include <string.h>

// ---------------- problem constants ----------------
#define TOK   2048
#define DDIM  1024
#define FDIM  4096
#define NEXP  8
#define FSH   512
#define TOPK  2
#define ROWCAP (NEXP*TOK)
#define NROWS  (ROWCAP + TOK)
#define NSLOT  9          // 8 routed + merged shared (slot 8)

// ---------------- scratch (device globals) ----------------
__device__ int   g_cnt[NEXP];
__device__ int   g_tok[ROWCAP];
__device__ int   g_rowof[TOK * TOPK];
__device__ float g_gw[TOK * TOPK];
__device__ __half g_x_hi[TOK * DDIM], g_x_lo[TOK * DDIM];
// W' : per slot 2*FDIM rows (g/u interleaved in 32-row blocks), K-major [r'][D]
__device__ __half g_wgT[(size_t)NSLOT * 2 * FDIM * DDIM];
__device__ __half g_w2T[(size_t)NSLOT * DDIM * FDIM];   // [slot][D][F] fp16
__device__ __half g_h_hi[(size_t)NROWS * FDIM];
__device__ __half g_h_lo[(size_t)NROWS * FDIM];
__device__ float g_orow[(size_t)NROWS * DDIM];

// ---------------- helpers ----------------
__device__ __forceinline__ uint32_t smem_u32(const void* p) {
    uint32_t a;
    asm("{ .reg .u64 t; cvta.to.shared.u64 t, %1; cvt.u32.u64 %0, t; }" : "=r"(a) : "l"(p));
    return a;
}
__device__ __forceinline__ void ldsm4(uint32_t* r, uint32_t a) {
    asm volatile("ldmatrix.sync.aligned.m8n8.x4.shared.b16 {%0,%1,%2,%3}, [%4];"
                 : "=r"(r[0]), "=r"(r[1]), "=r"(r[2]), "=r"(r[3]) : "r"(a));
}
__device__ __forceinline__ void mma_f16(float* c, const uint32_t* a, const uint32_t* b) {
    asm volatile(
        "mma.sync.aligned.m16n8k16.row.col.f32.f16.f16.f32 "
        "{%0,%1,%2,%3},{%4,%5,%6,%7},{%8,%9},{%0,%1,%2,%3};"
        : "+f"(c[0]), "+f"(c[1]), "+f"(c[2]), "+f"(c[3])
        : "r"(a[0]), "r"(a[1]), "r"(a[2]), "r"(a[3]), "r"(b[0]), "r"(b[1]));
}
#define CP16(dst, src) \
    asm volatile("cp.async.cg.shared.global [%0], [%1], 16;" :: "r"(dst), "l"(src))
#define CPCOMMIT() asm volatile("cp.async.commit_group;" ::: "memory")
#define CPWAIT1()  asm volatile("cp.async.wait_group 1;" ::: "memory")

__device__ __forceinline__ void split_h(float v, __half& h, __half& l) {
    h = __float2half_rn(v);
    l = __float2half_rn(v - __half2float(h));
}
__device__ __forceinline__ unsigned pk2h(__half a, __half b) {
    __half2 t = __halves2half2(a, b);
    unsigned r; memcpy(&r, &t, 4); return r;
}

// ============================ reset / gate ===============================
__global__ void k_reset() {
    if (threadIdx.x < NEXP) g_cnt[threadIdx.x] = 0;
}

__global__ void k_gate(const float* __restrict__ x, const float* __restrict__ gateW) {
    int gwarp = (blockIdx.x * blockDim.x + threadIdx.x) >> 5;
    int lane  = threadIdx.x & 31;
    if (gwarp >= TOK) return;
    const float* xr = x + (size_t)gwarp * DDIM;
    float xv[32];
#pragma unroll
    for (int i = 0; i < 32; i++) xv[i] = xr[lane + 32 * i];
    float logit[NEXP];
#pragma unroll
    for (int e = 0; e < NEXP; e++) {
        const float* wr = gateW + e * DDIM;
        float acc = 0.f;
#pragma unroll
        for (int i = 0; i < 32; i++) acc += xv[i] * wr[lane + 32 * i];
#pragma unroll
        for (int o = 16; o > 0; o >>= 1) acc += __shfl_xor_sync(0xffffffffu, acc, o);
        logit[e] = acc;
    }
    if (lane == 0) {
        float m = logit[0];
#pragma unroll
        for (int e = 1; e < NEXP; e++) m = fmaxf(m, logit[e]);
        float p[NEXP], den = 0.f;
#pragma unroll
        for (int e = 0; e < NEXP; e++) { p[e] = expf(logit[e] - m); den += p[e]; }
        int i1 = 0;
#pragma unroll
        for (int e = 1; e < NEXP; e++) if (p[e] > p[i1]) i1 = e;
        int i2 = (i1 == 0) ? 1 : 0;
#pragma unroll
        for (int e = 0; e < NEXP; e++) if (e != i2 && e != i1 && p[e] > p[i2]) i2 = e;
        int pos1 = atomicAdd(&g_cnt[i1], 1);
        int r1 = i1 * TOK + pos1;
        g_tok[r1] = gwarp;
        g_rowof[2 * gwarp + 0] = r1;
        g_gw[2 * gwarp + 0] = p[i1] / den;
        int pos2 = atomicAdd(&g_cnt[i2], 1);
        int r2 = i2 * TOK + pos2;
        g_tok[r2] = gwarp;
        g_rowof[2 * gwarp + 1] = r2;
        g_gw[2 * gwarp + 1] = p[i2] / den;
    }
}

// ===================== weight transpose (fp16) ===========================
// src: z-th block [R_rows=C? careful] -- src z-block is [Dsrc][Csrc] fp32 where
// Csrc is the output-row dim. dst row remap: goff>=0 -> GLU interleave.
__global__ __launch_bounds__(256) void k_transplit(
    const float* __restrict__ src, int dst_id, size_t extra,
    int R, int C, size_t sstride, size_t dstride, int goff)
{
    __shared__ float tile[32][33];
    __half* dst = (dst_id == 0) ? g_wgT : g_w2T;
    dst += extra;

    int z = blockIdx.z;
    const float* s = src + (size_t)z * sstride;
    size_t dbase = (size_t)z * dstride;
    int c0 = blockIdx.x * 32, r0 = blockIdx.y * 32;
    int tx = threadIdx.x & 31, ty = threadIdx.x >> 5;
#pragma unroll
    for (int i = 0; i < 4; i++)
        tile[ty + 8 * i][tx] = s[(size_t)(r0 + ty + 8 * i) * C + c0 + tx];
    __syncthreads();
#pragma unroll
    for (int i = 0; i < 4; i++) {
        float v = tile[tx][ty + 8 * i];
        int r = c0 + ty + 8 * i;              // output row (F-index)
        int rr = (goff >= 0) ? (((r >> 5) << 6) + goff + (r & 31)) : r;
        size_t o = dbase + (size_t)rr * R + r0 + tx;
        dst[o] = __float2half_rn(v);
    }
}

__global__ void k_xsplit(const float* __restrict__ x) {
    int i = blockIdx.x * blockDim.x + threadIdx.x;
    float v = x[i];
    __half h, l; split_h(v, h, l);
    g_x_hi[i] = h; g_x_lo[i] = l;
}

// ============================ GEMM tiles ================================
#define LDT 40          // smem row stride in fp16 elems (80B, conflict-free ldmatrix)
#define NSTG 3

// ---- GEMM1: 128(M) x 128(W'-rows) x 32, warps 4(M) x 2(N) ----
// elem offsets within one stage
#define G1_AH   0
#define G1_AL   5120
#define G1_B    10240                 // 128 rows x LDT
#define G1_STG  15360                 // elems / stage
#define G1_STGB (G1_STG * 2)          // 30720 bytes / stage
#define G1_SMEM (NSTG * G1_STGB + 512)

__global__ __launch_bounds__(256, 2) void k_gemm1() {
    const int z   = blockIdx.z;
    const int m0  = blockIdx.y * 128;
    const int n0p = blockIdx.x * 128;     // W' row base
    const int M   = (z < NEXP) ? g_cnt[z] : TOK;
    if (m0 >= M) return;
    const size_t rowbase = (z < NEXP) ? ((size_t)z * TOK + m0) : ((size_t)ROWCAP + m0);

    extern __shared__ __align__(16) char sm[];
    int* stok = (int*)(sm + NSTG * G1_STGB);
    const int tid = threadIdx.x;
    if (tid < 128) {
        int r = m0 + tid; if (r > M - 1) r = M - 1;
        stok[tid] = (z < NEXP) ? g_tok[z * TOK + r] : r;
    }
    __syncthreads();

    const uint32_t sbu = smem_u32(sm);
    const int ra = tid >> 2, c4 = tid & 3;
    const int tA0 = stok[ra], tA1 = stok[64 + ra];
    const __half* sxh0 = g_x_hi + (size_t)tA0 * DDIM + c4 * 8;
    const __half* sxh1 = g_x_hi + (size_t)tA1 * DDIM + c4 * 8;
    const __half* sxl0 = g_x_lo + (size_t)tA0 * DDIM + c4 * 8;
    const __half* sxl1 = g_x_lo + (size_t)tA1 * DDIM + c4 * 8;
    const size_t bsrc = ((size_t)z * 2 * FDIM + n0p + ra) * DDIM + c4 * 8;
    const __half *sB0 = g_wgT + bsrc, *sB1 = sB0 + (size_t)64 * DDIM;

    const uint32_t dA0 = (G1_AH + ra * LDT + c4 * 8) * 2;
    const uint32_t dA1 = dA0 + 64 * LDT * 2;
    const uint32_t dL0 = dA0 + (G1_AL - G1_AH) * 2;
    const uint32_t dL1 = dL0 + 64 * LDT * 2;
    const uint32_t dB0 = (G1_B + ra * LDT + c4 * 8) * 2;
    const uint32_t dB1 = dB0 + 64 * LDT * 2;

    const int lane = tid & 31, w = tid >> 5;
    const int wm = w >> 1, wn = w & 1;
    const int qr = lane >> 2, qc = lane & 3;
    const uint32_t aoff = ((wm * 32 + (lane & 15)) * LDT + (lane >> 4) * 8) * 2;
    const uint32_t boff = (G1_B + (wn * 64 + (lane & 7) + ((lane >> 4) & 1) * 8) * LDT
                           + ((lane >> 3) & 1) * 8) * 2;

    float acc[2][8][4] = {};

#define G1_LOAD(it) do { \
    const int k0 = (it) * 32; \
    const uint32_t db = sbu + ((it) % NSTG) * G1_STGB; \
    CP16(db + dA0, sxh0 + k0); \
    CP16(db + dA1, sxh1 + k0); \
    CP16(db + dL0, sxl0 + k0); \
    CP16(db + dL1, sxl1 + k0); \
    CP16(db + dB0, sB0 + k0); \
    CP16(db + dB1, sB1 + k0); \
    CPCOMMIT(); \
} while (0)

    G1_LOAD(0);
    G1_LOAD(1);

    const int NIT = DDIM / 32;
    for (int it = 0; it < NIT; it++) {
        CPWAIT1();
        __syncthreads();
        if (it + 2 < NIT) G1_LOAD(it + 2); else CPCOMMIT();
        const uint32_t stg = sbu + (it % NSTG) * G1_STGB;
#pragma unroll
        for (int ks = 0; ks < 32; ks += 16) {
            uint32_t ah[2][4], al[2][4];
#pragma unroll
            for (int mt = 0; mt < 2; mt++) {
                ldsm4(ah[mt], stg + aoff + mt * (16 * LDT * 2) + ks * 2);
                ldsm4(al[mt], stg + (G1_AL * 2) + aoff + mt * (16 * LDT * 2) + ks * 2);
            }
#pragma unroll
            for (int nh = 0; nh < 4; nh++) {
                uint32_t bb[4];
                ldsm4(bb, stg + boff + nh * (16 * LDT * 2) + ks * 2);
#pragma unroll
                for (int t = 0; t < 2; t++) {
                    const int nt = nh * 2 + t;
#pragma unroll
                    for (int mt = 0; mt < 2; mt++) {
                        mma_f16(acc[mt][nt], ah[mt], bb + 2 * t);
                        mma_f16(acc[mt][nt], al[mt], bb + 2 * t);
                    }
                }
            }
        }
    }
#undef G1_LOAD

    // epilogue: GLU pairing in-register: g = acc[mt][nt], u = acc[mt][nt+4]
    // warp f-col base: blockIdx.x*64 + wn*32
    const int fb = blockIdx.x * 64 + wn * 32;
#pragma unroll
    for (int mt = 0; mt < 2; mt++)
#pragma unroll
        for (int nt = 0; nt < 4; nt++) {
            const int R = wm * 32 + mt * 16 + qr;
            const int C = fb + nt * 8 + 2 * qc;
#pragma unroll
            for (int half = 0; half < 2; half++) {
                const int r = R + half * 8;
                float g0 = acc[mt][nt][2 * half],     u0 = acc[mt][nt + 4][2 * half];
                float g1 = acc[mt][nt][2 * half + 1], u1 = acc[mt][nt + 4][2 * half + 1];
                float o0 = g0 / (1.f + __expf(-g0)) * u0;
                float o1 = g1 / (1.f + __expf(-g1)) * u1;
                __half h0, l0, h1, l1;
                split_h(o0, h0, l0); split_h(o1, h1, l1);
                const size_t idx = (rowbase + r) * (size_t)FDIM + C;
                *(unsigned*)&g_h_hi[idx] = pk2h(h0, h1);
                *(unsigned*)&g_h_lo[idx] = pk2h(l0, l1);
            }
        }
}

// ---- GEMM2: 128 x 64 x 32, warps 4 x 2 over (32M x 32N) ----
#define G2_AH   0
#define G2_AL   5120
#define G2_B    10240
#define G2_STG  12800
#define G2_STGB (G2_STG * 2)
#define G2_SMEM (NSTG * G2_STGB)

__global__ __launch_bounds__(256, 2) void k_gemm2() {
    const int z  = blockIdx.z;
    const int m0 = blockIdx.y * 128;
    const int n0 = blockIdx.x * 64;
    const int M  = (z < NEXP) ? g_cnt[z] : TOK;
    if (m0 >= M) return;
    const size_t rowbase = (z < NEXP) ? ((size_t)z * TOK + m0) : ((size_t)ROWCAP + m0);

    extern __shared__ __align__(16) char sm[];
    const uint32_t sbu = smem_u32(sm);
    const int tid = threadIdx.x;
    const int ra = tid >> 2, c4 = tid & 3;

    const __half* sah0 = g_h_hi + (rowbase + ra) * (size_t)FDIM + c4 * 8;
    const __half* sah1 = g_h_hi + (rowbase + 64 + ra) * (size_t)FDIM + c4 * 8;
    const __half* sal0 = g_h_lo + (rowbase + ra) * (size_t)FDIM + c4 * 8;
    const __half* sal1 = g_h_lo + (rowbase + 64 + ra) * (size_t)FDIM + c4 * 8;
    const size_t bsrc = ((size_t)z * DDIM + n0 + ra) * FDIM + c4 * 8;
    const __half* sB = g_w2T + bsrc;

    const uint32_t dA0 = (G2_AH + ra * LDT + c4 * 8) * 2;
    const uint32_t dA1 = dA0 + 64 * LDT * 2;
    const uint32_t dL0 = dA0 + (G2_AL - G2_AH) * 2;
    const uint32_t dL1 = dL0 + 64 * LDT * 2;
    const uint32_t dB  = (G2_B + ra * LDT + c4 * 8) * 2;

    const int lane = tid & 31, w = tid >> 5;
    const int wm = w >> 1, wn = w & 1;
    const int qr = lane >> 2, qc = lane & 3;
    const uint32_t aoff = ((wm * 32 + (lane & 15)) * LDT + (lane >> 4) * 8) * 2;
    const uint32_t boff = (G2_B + (wn * 32 + (lane & 7) + ((lane >> 4) & 1) * 8) * LDT
                           + ((lane >> 3) & 1) * 8) * 2;

    float acc[2][4][4] = {};

#define G2_LOAD(it) do { \
    const int k0 = (it) * 32; \
    const uint32_t db = sbu + ((it) % NSTG) * G2_STGB; \
    CP16(db + dA0, sah0 + k0); \
    CP16(db + dA1, sah1 + k0); \
    CP16(db + dL0, sal0 + k0); \
    CP16(db + dL1, sal1 + k0); \
    CP16(db + dB, sB + k0); \
    CPCOMMIT(); \
} while (0)

    G2_LOAD(0);
    G2_LOAD(1);

    const int NIT = FDIM / 32;
    for (int it = 0; it < NIT; it++) {
        CPWAIT1();
        __syncthreads();
        if (it + 2 < NIT) G2_LOAD(it + 2); else CPCOMMIT();
        const uint32_t stg = sbu + (it % NSTG) * G2_STGB;
#pragma unroll
        for (int ks = 0; ks < 32; ks += 16) {
            uint32_t ah[2][4], al[2][4];
#pragma unroll
            for (int mt = 0; mt < 2; mt++) {
                ldsm4(ah[mt], stg + aoff + mt * (16 * LDT * 2) + ks * 2);
                ldsm4(al[mt], stg + (G2_AL * 2) + aoff + mt * (16 * LDT * 2) + ks * 2);
            }
#pragma unroll
            for (int nh = 0; nh < 2; nh++) {
                uint32_t bb[4];
                ldsm4(bb, stg + boff + nh * (16 * LDT * 2) + ks * 2);
#pragma unroll
                for (int t = 0; t < 2; t++) {
                    const int nt = nh * 2 + t;
#pragma unroll
                    for (int mt = 0; mt < 2; mt++) {
                        mma_f16(acc[mt][nt], ah[mt], bb + 2 * t);
                        mma_f16(acc[mt][nt], al[mt], bb + 2 * t);
                    }
                }
            }
        }
    }
#undef G2_LOAD

#pragma unroll
    for (int mt = 0; mt < 2; mt++)
#pragma unroll
        for (int nt = 0; nt < 4; nt++) {
            const int R = wm * 32 + mt * 16 + qr;
            const int C = wn * 32 + nt * 8 + 2 * qc;
#pragma unroll
            for (int half = 0; half < 2; half++) {
                const int r = R + half * 8;
                float2 o;
                o.x = acc[mt][nt][2 * half];
                o.y = acc[mt][nt][2 * half + 1];
                *(float2*)&g_orow[(rowbase + r) * (size_t)DDIM + n0 + C] = o;
            }
        }
}

// ============================ combine ===================================
__global__ void k_combine(float* __restrict__ out) {
    int idx = blockIdx.x * blockDim.x + threadIdx.x;
    if (idx >= TOK * DDIM) return;
    int t = idx >> 10;
    int d = idx & (DDIM - 1);
    float sh = g_orow[((size_t)ROWCAP + t) * DDIM + d];
    int   r0 = g_rowof[2 * t], r1 = g_rowof[2 * t + 1];
    float v = 0.0625f * sh
            + 0.5f * (g_gw[2 * t] * g_orow[(size_t)r0 * DDIM + d]
                    + g_gw[2 * t + 1] * g_orow[(size_t)r1 * DDIM + d]);
    out[idx] = v;
}

// ============================ launch ====================================
extern "C" void kernel_launch(void* const* d_in, const int* in_sizes, int n_in,
                              void* d_out, int out_size) {
    const float* x   = (const float*)d_in[0];
    const float* gW  = (const float*)d_in[1];
    const float* w1e = (const float*)d_in[2];
    const float* w3e = (const float*)d_in[3];
    const float* w2e = (const float*)d_in[4];
    const float* w1s = (const float*)d_in[5];
    const float* w3s = (const float*)d_in[6];
    const float* w2s = (const float*)d_in[7];
    float* out = (float*)d_out;

    cudaFuncSetAttribute(k_gemm1, cudaFuncAttributeMaxDynamicSharedMemorySize, G1_SMEM);
    cudaFuncSetAttribute(k_gemm2, cudaFuncAttributeMaxDynamicSharedMemorySize, G2_SMEM);

    k_reset<<<1, 32>>>();
    k_gate<<<TOK / 8, 256>>>(x, gW);
    k_xsplit<<<TOK * DDIM / 256, 256>>>(x);

    // routed: w1/w3 -> interleaved W' slots 0..7; w2 -> w2T slots 0..7
    k_transplit<<<dim3(FDIM / 32, DDIM / 32, NEXP), 256>>>(
        w1e, 0, 0, DDIM, FDIM, (size_t)DDIM * FDIM, (size_t)2 * FDIM * DDIM, 0);
    k_transplit<<<dim3(FDIM / 32, DDIM / 32, NEXP), 256>>>(
        w3e, 0, 0, DDIM, FDIM, (size_t)DDIM * FDIM, (size_t)2 * FDIM * DDIM, 32);
    k_transplit<<<dim3(DDIM / 32, FDIM / 32, NEXP), 256>>>(
        w2e, 1, 0, FDIM, DDIM, (size_t)FDIM * DDIM, (size_t)DDIM * FDIM, -1);
    // shared experts -> slot 8 (block-concatenated); per-z W' span = 1024 rows
    k_transplit<<<dim3(FSH / 32, DDIM / 32, NEXP), 256>>>(
        w1s, 0, (size_t)NEXP * 2 * FDIM * DDIM, DDIM, FSH, (size_t)DDIM * FSH,
        (size_t)1024 * DDIM, 0);
    k_transplit<<<dim3(FSH / 32, DDIM / 32, NEXP), 256>>>(
        w3s, 0, (size_t)NEXP * 2 * FDIM * DDIM, DDIM, FSH, (size_t)DDIM * FSH,
        (size_t)1024 * DDIM, 32);
    k_transplit<<<dim3(DDIM / 32, FDIM / 32, 1), 256>>>(
        w2s, 1, (size_t)NEXP * DDIM * FDIM, FDIM, DDIM, 0, 0, -1);

    k_gemm1<<<dim3(2 * FDIM / 128, TOK / 128, NSLOT), 256, G1_SMEM>>>();
    k_gemm2<<<dim3(DDIM / 64, TOK / 128, NSLOT), 256, G2_SMEM>>>();
    k_combine<<<(TOK * DDIM) / 256, 256>>>(out);
}

// round 7
// speedup vs baseline: 4.6377x; 1.0036x over previous
#include <cuda_runtime.h>
#include <cuda_fp16.h>
#include <math.h>
#include <cstdint>
#include <string.h>

// ---------------- problem constants ----------------
#define TOK   2048
#define DDIM  1024
#define FDIM  4096
#define NEXP  8
#define FSH   512
#define TOPK  2
#define ROWCAP (NEXP*TOK)
#define NROWS  (ROWCAP + TOK)
#define NSLOT  9          // 8 routed + merged shared (slot 8)

// ---------------- scratch (device globals) ----------------
__device__ int   g_cnt[NEXP];
__device__ int   g_tok[ROWCAP];
__device__ int   g_rowof[TOK * TOPK];
__device__ float g_gw[TOK * TOPK];
__device__ __half g_x_hi[TOK * DDIM], g_x_lo[TOK * DDIM];
// W' : per slot 2*FDIM rows (g/u interleaved in 32-row blocks), K-major [r'][D]
__device__ __half g_wgT[(size_t)NSLOT * 2 * FDIM * DDIM];
__device__ __half g_w2T[(size_t)NSLOT * DDIM * FDIM];   // [slot][D][F] fp16
__device__ __half g_h_hi[(size_t)NROWS * FDIM];
__device__ __half g_h_lo[(size_t)NROWS * FDIM];
__device__ float g_orow[(size_t)NROWS * DDIM];

// ---------------- helpers ----------------
__device__ __forceinline__ uint32_t smem_u32(const void* p) {
    uint32_t a;
    asm("{ .reg .u64 t; cvta.to.shared.u64 t, %1; cvt.u32.u64 %0, t; }" : "=r"(a) : "l"(p));
    return a;
}
__device__ __forceinline__ void ldsm4(uint32_t* r, uint32_t a) {
    asm volatile("ldmatrix.sync.aligned.m8n8.x4.shared.b16 {%0,%1,%2,%3}, [%4];"
                 : "=r"(r[0]), "=r"(r[1]), "=r"(r[2]), "=r"(r[3]) : "r"(a));
}
__device__ __forceinline__ void mma_f16(float* c, const uint32_t* a, const uint32_t* b) {
    asm volatile(
        "mma.sync.aligned.m16n8k16.row.col.f32.f16.f16.f32 "
        "{%0,%1,%2,%3},{%4,%5,%6,%7},{%8,%9},{%0,%1,%2,%3};"
        : "+f"(c[0]), "+f"(c[1]), "+f"(c[2]), "+f"(c[3])
        : "r"(a[0]), "r"(a[1]), "r"(a[2]), "r"(a[3]), "r"(b[0]), "r"(b[1]));
}
#define CP16(dst, src) \
    asm volatile("cp.async.cg.shared.global [%0], [%1], 16;" :: "r"(dst), "l"(src))
#define CPCOMMIT() asm volatile("cp.async.commit_group;" ::: "memory")
#define CPWAIT1()  asm volatile("cp.async.wait_group 1;" ::: "memory")

__device__ __forceinline__ void split_h(float v, __half& h, __half& l) {
    h = __float2half_rn(v);
    l = __float2half_rn(v - __half2float(h));
}
__device__ __forceinline__ unsigned pk2h(__half a, __half b) {
    __half2 t = __halves2half2(a, b);
    unsigned r; memcpy(&r, &t, 4); return r;
}

// ============================ reset / gate ===============================
__global__ void k_reset() {
    if (threadIdx.x < NEXP) g_cnt[threadIdx.x] = 0;
}

__global__ void k_gate(const float* __restrict__ x, const float* __restrict__ gateW) {
    int gwarp = (blockIdx.x * blockDim.x + threadIdx.x) >> 5;
    int lane  = threadIdx.x & 31;
    if (gwarp >= TOK) return;
    const float* xr = x + (size_t)gwarp * DDIM;
    float xv[32];
#pragma unroll
    for (int i = 0; i < 32; i++) xv[i] = xr[lane + 32 * i];
    float logit[NEXP];
#pragma unroll
    for (int e = 0; e < NEXP; e++) {
        const float* wr = gateW + e * DDIM;
        float acc = 0.f;
#pragma unroll
        for (int i = 0; i < 32; i++) acc += xv[i] * wr[lane + 32 * i];
#pragma unroll
        for (int o = 16; o > 0; o >>= 1) acc += __shfl_xor_sync(0xffffffffu, acc, o);
        logit[e] = acc;
    }
    if (lane == 0) {
        float m = logit[0];
#pragma unroll
        for (int e = 1; e < NEXP; e++) m = fmaxf(m, logit[e]);
        float p[NEXP], den = 0.f;
#pragma unroll
        for (int e = 0; e < NEXP; e++) { p[e] = expf(logit[e] - m); den += p[e]; }
        int i1 = 0;
#pragma unroll
        for (int e = 1; e < NEXP; e++) if (p[e] > p[i1]) i1 = e;
        int i2 = (i1 == 0) ? 1 : 0;
#pragma unroll
        for (int e = 0; e < NEXP; e++) if (e != i2 && e != i1 && p[e] > p[i2]) i2 = e;
        int pos1 = atomicAdd(&g_cnt[i1], 1);
        int r1 = i1 * TOK + pos1;
        g_tok[r1] = gwarp;
        g_rowof[2 * gwarp + 0] = r1;
        g_gw[2 * gwarp + 0] = p[i1] / den;
        int pos2 = atomicAdd(&g_cnt[i2], 1);
        int r2 = i2 * TOK + pos2;
        g_tok[r2] = gwarp;
        g_rowof[2 * gwarp + 1] = r2;
        g_gw[2 * gwarp + 1] = p[i2] / den;
    }
}

// ===================== weight transpose (fp16) ===========================
// src: z-th block [R_rows=C? careful] -- src z-block is [Dsrc][Csrc] fp32 where
// Csrc is the output-row dim. dst row remap: goff>=0 -> GLU interleave.
__global__ __launch_bounds__(256) void k_transplit(
    const float* __restrict__ src, int dst_id, size_t extra,
    int R, int C, size_t sstride, size_t dstride, int goff)
{
    __shared__ float tile[32][33];
    __half* dst = (dst_id == 0) ? g_wgT : g_w2T;
    dst += extra;

    int z = blockIdx.z;
    const float* s = src + (size_t)z * sstride;
    size_t dbase = (size_t)z * dstride;
    int c0 = blockIdx.x * 32, r0 = blockIdx.y * 32;
    int tx = threadIdx.x & 31, ty = threadIdx.x >> 5;
#pragma unroll
    for (int i = 0; i < 4; i++)
        tile[ty + 8 * i][tx] = s[(size_t)(r0 + ty + 8 * i) * C + c0 + tx];
    __syncthreads();
#pragma unroll
    for (int i = 0; i < 4; i++) {
        float v = tile[tx][ty + 8 * i];
        int r = c0 + ty + 8 * i;              // output row (F-index)
        int rr = (goff >= 0) ? (((r >> 5) << 6) + goff + (r & 31)) : r;
        size_t o = dbase + (size_t)rr * R + r0 + tx;
        dst[o] = __float2half_rn(v);
    }
}

__global__ void k_xsplit(const float* __restrict__ x) {
    int i = blockIdx.x * blockDim.x + threadIdx.x;
    float v = x[i];
    __half h, l; split_h(v, h, l);
    g_x_hi[i] = h; g_x_lo[i] = l;
}

// ============================ GEMM tiles ================================
#define LDT 40          // smem row stride in fp16 elems (80B, conflict-free ldmatrix)
#define NSTG 3

// ---- GEMM1: 128(M) x 128(W'-rows) x 32, warps 4(M) x 2(N) ----
// elem offsets within one stage
#define G1_AH   0
#define G1_AL   5120
#define G1_B    10240                 // 128 rows x LDT
#define G1_STG  15360                 // elems / stage
#define G1_STGB (G1_STG * 2)          // 30720 bytes / stage
#define G1_SMEM (NSTG * G1_STGB + 512)

__global__ __launch_bounds__(256, 2) void k_gemm1() {
    const int z   = blockIdx.z;
    const int m0  = blockIdx.y * 128;
    const int n0p = blockIdx.x * 128;     // W' row base
    const int M   = (z < NEXP) ? g_cnt[z] : TOK;
    if (m0 >= M) return;
    const size_t rowbase = (z < NEXP) ? ((size_t)z * TOK + m0) : ((size_t)ROWCAP + m0);

    extern __shared__ __align__(16) char sm[];
    int* stok = (int*)(sm + NSTG * G1_STGB);
    const int tid = threadIdx.x;
    if (tid < 128) {
        int r = m0 + tid; if (r > M - 1) r = M - 1;
        stok[tid] = (z < NEXP) ? g_tok[z * TOK + r] : r;
    }
    __syncthreads();

    const uint32_t sbu = smem_u32(sm);
    const int ra = tid >> 2, c4 = tid & 3;
    const int tA0 = stok[ra], tA1 = stok[64 + ra];
    const __half* sxh0 = g_x_hi + (size_t)tA0 * DDIM + c4 * 8;
    const __half* sxh1 = g_x_hi + (size_t)tA1 * DDIM + c4 * 8;
    const __half* sxl0 = g_x_lo + (size_t)tA0 * DDIM + c4 * 8;
    const __half* sxl1 = g_x_lo + (size_t)tA1 * DDIM + c4 * 8;
    const size_t bsrc = ((size_t)z * 2 * FDIM + n0p + ra) * DDIM + c4 * 8;
    const __half *sB0 = g_wgT + bsrc, *sB1 = sB0 + (size_t)64 * DDIM;

    const uint32_t dA0 = (G1_AH + ra * LDT + c4 * 8) * 2;
    const uint32_t dA1 = dA0 + 64 * LDT * 2;
    const uint32_t dL0 = dA0 + (G1_AL - G1_AH) * 2;
    const uint32_t dL1 = dL0 + 64 * LDT * 2;
    const uint32_t dB0 = (G1_B + ra * LDT + c4 * 8) * 2;
    const uint32_t dB1 = dB0 + 64 * LDT * 2;

    const int lane = tid & 31, w = tid >> 5;
    const int wm = w >> 1, wn = w & 1;
    const int qr = lane >> 2, qc = lane & 3;
    const uint32_t aoff = ((wm * 32 + (lane & 15)) * LDT + (lane >> 4) * 8) * 2;
    const uint32_t boff = (G1_B + (wn * 64 + (lane & 7) + ((lane >> 4) & 1) * 8) * LDT
                           + ((lane >> 3) & 1) * 8) * 2;

    float acc[2][8][4] = {};

#define G1_LOAD(it) do { \
    const int k0 = (it) * 32; \
    const uint32_t db = sbu + ((it) % NSTG) * G1_STGB; \
    CP16(db + dA0, sxh0 + k0); \
    CP16(db + dA1, sxh1 + k0); \
    CP16(db + dL0, sxl0 + k0); \
    CP16(db + dL1, sxl1 + k0); \
    CP16(db + dB0, sB0 + k0); \
    CP16(db + dB1, sB1 + k0); \
    CPCOMMIT(); \
} while (0)

    G1_LOAD(0);
    G1_LOAD(1);

    const int NIT = DDIM / 32;
    for (int it = 0; it < NIT; it++) {
        CPWAIT1();
        __syncthreads();
        if (it + 2 < NIT) G1_LOAD(it + 2); else CPCOMMIT();
        const uint32_t stg = sbu + (it % NSTG) * G1_STGB;
#pragma unroll
        for (int ks = 0; ks < 32; ks += 16) {
            uint32_t ah[2][4], al[2][4];
#pragma unroll
            for (int mt = 0; mt < 2; mt++) {
                ldsm4(ah[mt], stg + aoff + mt * (16 * LDT * 2) + ks * 2);
                ldsm4(al[mt], stg + (G1_AL * 2) + aoff + mt * (16 * LDT * 2) + ks * 2);
            }
#pragma unroll
            for (int nh = 0; nh < 4; nh++) {
                uint32_t bb[4];
                ldsm4(bb, stg + boff + nh * (16 * LDT * 2) + ks * 2);
#pragma unroll
                for (int t = 0; t < 2; t++) {
                    const int nt = nh * 2 + t;
#pragma unroll
                    for (int mt = 0; mt < 2; mt++) {
                        mma_f16(acc[mt][nt], ah[mt], bb + 2 * t);
                        mma_f16(acc[mt][nt], al[mt], bb + 2 * t);
                    }
                }
            }
        }
    }
#undef G1_LOAD

    // epilogue: GLU pairing in-register: g = acc[mt][nt], u = acc[mt][nt+4]
    // warp f-col base: blockIdx.x*64 + wn*32
    const int fb = blockIdx.x * 64 + wn * 32;
#pragma unroll
    for (int mt = 0; mt < 2; mt++)
#pragma unroll
        for (int nt = 0; nt < 4; nt++) {
            const int R = wm * 32 + mt * 16 + qr;
            const int C = fb + nt * 8 + 2 * qc;
#pragma unroll
            for (int half = 0; half < 2; half++) {
                const int r = R + half * 8;
                float g0 = acc[mt][nt][2 * half],     u0 = acc[mt][nt + 4][2 * half];
                float g1 = acc[mt][nt][2 * half + 1], u1 = acc[mt][nt + 4][2 * half + 1];
                float o0 = g0 / (1.f + __expf(-g0)) * u0;
                float o1 = g1 / (1.f + __expf(-g1)) * u1;
                __half h0, l0, h1, l1;
                split_h(o0, h0, l0); split_h(o1, h1, l1);
                const size_t idx = (rowbase + r) * (size_t)FDIM + C;
                *(unsigned*)&g_h_hi[idx] = pk2h(h0, h1);
                *(unsigned*)&g_h_lo[idx] = pk2h(l0, l1);
            }
        }
}

// ---- GEMM2: 128 x 64 x 32, warps 4 x 2 over (32M x 32N) ----
#define G2_AH   0
#define G2_AL   5120
#define G2_B    10240
#define G2_STG  12800
#define G2_STGB (G2_STG * 2)
#define G2_SMEM (NSTG * G2_STGB)

__global__ __launch_bounds__(256, 2) void k_gemm2() {
    const int z  = blockIdx.z;
    const int m0 = blockIdx.y * 128;
    const int n0 = blockIdx.x * 64;
    const int M  = (z < NEXP) ? g_cnt[z] : TOK;
    if (m0 >= M) return;
    const size_t rowbase = (z < NEXP) ? ((size_t)z * TOK + m0) : ((size_t)ROWCAP + m0);

    extern __shared__ __align__(16) char sm[];
    const uint32_t sbu = smem_u32(sm);
    const int tid = threadIdx.x;
    const int ra = tid >> 2, c4 = tid & 3;

    const __half* sah0 = g_h_hi + (rowbase + ra) * (size_t)FDIM + c4 * 8;
    const __half* sah1 = g_h_hi + (rowbase + 64 + ra) * (size_t)FDIM + c4 * 8;
    const __half* sal0 = g_h_lo + (rowbase + ra) * (size_t)FDIM + c4 * 8;
    const __half* sal1 = g_h_lo + (rowbase + 64 + ra) * (size_t)FDIM + c4 * 8;
    const size_t bsrc = ((size_t)z * DDIM + n0 + ra) * FDIM + c4 * 8;
    const __half* sB = g_w2T + bsrc;

    const uint32_t dA0 = (G2_AH + ra * LDT + c4 * 8) * 2;
    const uint32_t dA1 = dA0 + 64 * LDT * 2;
    const uint32_t dL0 = dA0 + (G2_AL - G2_AH) * 2;
    const uint32_t dL1 = dL0 + 64 * LDT * 2;
    const uint32_t dB  = (G2_B + ra * LDT + c4 * 8) * 2;

    const int lane = tid & 31, w = tid >> 5;
    const int wm = w >> 1, wn = w & 1;
    const int qr = lane >> 2, qc = lane & 3;
    const uint32_t aoff = ((wm * 32 + (lane & 15)) * LDT + (lane >> 4) * 8) * 2;
    const uint32_t boff = (G2_B + (wn * 32 + (lane & 7) + ((lane >> 4) & 1) * 8) * LDT
                           + ((lane >> 3) & 1) * 8) * 2;

    float acc[2][4][4] = {};

#define G2_LOAD(it) do { \
    const int k0 = (it) * 32; \
    const uint32_t db = sbu + ((it) % NSTG) * G2_STGB; \
    CP16(db + dA0, sah0 + k0); \
    CP16(db + dA1, sah1 + k0); \
    CP16(db + dL0, sal0 + k0); \
    CP16(db + dL1, sal1 + k0); \
    CP16(db + dB, sB + k0); \
    CPCOMMIT(); \
} while (0)

    G2_LOAD(0);
    G2_LOAD(1);

    const int NIT = FDIM / 32;
    for (int it = 0; it < NIT; it++) {
        CPWAIT1();
        __syncthreads();
        if (it + 2 < NIT) G2_LOAD(it + 2); else CPCOMMIT();
        const uint32_t stg = sbu + (it % NSTG) * G2_STGB;
#pragma unroll
        for (int ks = 0; ks < 32; ks += 16) {
            uint32_t ah[2][4], al[2][4];
#pragma unroll
            for (int mt = 0; mt < 2; mt++) {
                ldsm4(ah[mt], stg + aoff + mt * (16 * LDT * 2) + ks * 2);
                ldsm4(al[mt], stg + (G2_AL * 2) + aoff + mt * (16 * LDT * 2) + ks * 2);
            }
#pragma unroll
            for (int nh = 0; nh < 2; nh++) {
                uint32_t bb[4];
                ldsm4(bb, stg + boff + nh * (16 * LDT * 2) + ks * 2);
#pragma unroll
                for (int t = 0; t < 2; t++) {
                    const int nt = nh * 2 + t;
#pragma unroll
                    for (int mt = 0; mt < 2; mt++) {
                        mma_f16(acc[mt][nt], ah[mt], bb + 2 * t);
                        mma_f16(acc[mt][nt], al[mt], bb + 2 * t);
                    }
                }
            }
        }
    }
#undef G2_LOAD

#pragma unroll
    for (int mt = 0; mt < 2; mt++)
#pragma unroll
        for (int nt = 0; nt < 4; nt++) {
            const int R = wm * 32 + mt * 16 + qr;
            const int C = wn * 32 + nt * 8 + 2 * qc;
#pragma unroll
            for (int half = 0; half < 2; half++) {
                const int r = R + half * 8;
                float2 o;
                o.x = acc[mt][nt][2 * half];
                o.y = acc[mt][nt][2 * half + 1];
                *(float2*)&g_orow[(rowbase + r) * (size_t)DDIM + n0 + C] = o;
            }
        }
}

// ============================ combine ===================================
__global__ void k_combine(float* __restrict__ out) {
    int idx = blockIdx.x * blockDim.x + threadIdx.x;
    if (idx >= TOK * DDIM) return;
    int t = idx >> 10;
    int d = idx & (DDIM - 1);
    float sh = g_orow[((size_t)ROWCAP + t) * DDIM + d];
    int   r0 = g_rowof[2 * t], r1 = g_rowof[2 * t + 1];
    float v = 0.0625f * sh
            + 0.5f * (g_gw[2 * t] * g_orow[(size_t)r0 * DDIM + d]
                    + g_gw[2 * t + 1] * g_orow[(size_t)r1 * DDIM + d]);
    out[idx] = v;
}

// ============================ launch ====================================
extern "C" void kernel_launch(void* const* d_in, const int* in_sizes, int n_in,
                              void* d_out, int out_size) {
    const float* x   = (const float*)d_in[0];
    const float* gW  = (const float*)d_in[1];
    const float* w1e = (const float*)d_in[2];
    const float* w3e = (const float*)d_in[3];
    const float* w2e = (const float*)d_in[4];
    const float* w1s = (const float*)d_in[5];
    const float* w3s = (const float*)d_in[6];
    const float* w2s = (const float*)d_in[7];
    float* out = (float*)d_out;

    cudaFuncSetAttribute(k_gemm1, cudaFuncAttributeMaxDynamicSharedMemorySize, G1_SMEM);
    cudaFuncSetAttribute(k_gemm2, cudaFuncAttributeMaxDynamicSharedMemorySize, G2_SMEM);

    k_reset<<<1, 32>>>();
    k_gate<<<TOK / 8, 256>>>(x, gW);
    k_xsplit<<<TOK * DDIM / 256, 256>>>(x);

    // routed: w1/w3 -> interleaved W' slots 0..7; w2 -> w2T slots 0..7
    k_transplit<<<dim3(FDIM / 32, DDIM / 32, NEXP), 256>>>(
        w1e, 0, 0, DDIM, FDIM, (size_t)DDIM * FDIM, (size_t)2 * FDIM * DDIM, 0);
    k_transplit<<<dim3(FDIM / 32, DDIM / 32, NEXP), 256>>>(
        w3e, 0, 0, DDIM, FDIM, (size_t)DDIM * FDIM, (size_t)2 * FDIM * DDIM, 32);
    k_transplit<<<dim3(DDIM / 32, FDIM / 32, NEXP), 256>>>(
        w2e, 1, 0, FDIM, DDIM, (size_t)FDIM * DDIM, (size_t)DDIM * FDIM, -1);
    // shared experts -> slot 8 (block-concatenated); per-z W' span = 1024 rows
    k_transplit<<<dim3(FSH / 32, DDIM / 32, NEXP), 256>>>(
        w1s, 0, (size_t)NEXP * 2 * FDIM * DDIM, DDIM, FSH, (size_t)DDIM * FSH,
        (size_t)1024 * DDIM, 0);
    k_transplit<<<dim3(FSH / 32, DDIM / 32, NEXP), 256>>>(
        w3s, 0, (size_t)NEXP * 2 * FDIM * DDIM, DDIM, FSH, (size_t)DDIM * FSH,
        (size_t)1024 * DDIM, 32);
    k_transplit<<<dim3(DDIM / 32, FDIM / 32, 1), 256>>>(
        w2s, 1, (size_t)NEXP * DDIM * FDIM, FDIM, DDIM, 0, 0, -1);

    k_gemm1<<<dim3(2 * FDIM / 128, TOK / 128, NSLOT), 256, G1_SMEM>>>();
    k_gemm2<<<dim3(DDIM / 64, TOK / 128, NSLOT), 256, G2_SMEM>>>();
    k_combine<<<(TOK * DDIM) / 256, 256>>>(out);
}

// round 8
// speedup vs baseline: 6.7123x; 1.4473x over previous
#include <cuda_runtime.h>
#include <cuda_fp16.h>
#include <math.h>
#include <cstdint>
#include <string.h>

// ---------------- problem constants ----------------
#define TOK   2048
#define DDIM  1024
#define FDIM  4096
#define NEXP  8
#define FSH   512
#define TOPK  2
#define ROWCAP (NEXP*TOK)
#define NROWS  (ROWCAP + TOK)
#define NSLOT  9          // 8 routed + merged shared (slot 8)

// ---------------- scratch (device globals) ----------------
__device__ int   g_cnt[NEXP];
__device__ int   g_tok[ROWCAP];
__device__ int   g_rowof[TOK * TOPK];
__device__ float g_gw[TOK * TOPK];
__device__ __half g_x[TOK * DDIM];
// W' : per slot 2*FDIM rows (g/u interleaved in 32-row blocks), K-major [r'][D]
__device__ __half g_wgT[(size_t)NSLOT * 2 * FDIM * DDIM];
__device__ __half g_w2T[(size_t)NSLOT * DDIM * FDIM];   // [slot][D][F] fp16
__device__ __half g_h[(size_t)NROWS * FDIM];
__device__ float g_orow[(size_t)NROWS * DDIM];

// ---------------- helpers ----------------
__device__ __forceinline__ uint32_t smem_u32(const void* p) {
    uint32_t a;
    asm("{ .reg .u64 t; cvta.to.shared.u64 t, %1; cvt.u32.u64 %0, t; }" : "=r"(a) : "l"(p));
    return a;
}
__device__ __forceinline__ void ldsm4(uint32_t* r, uint32_t a) {
    asm volatile("ldmatrix.sync.aligned.m8n8.x4.shared.b16 {%0,%1,%2,%3}, [%4];"
                 : "=r"(r[0]), "=r"(r[1]), "=r"(r[2]), "=r"(r[3]) : "r"(a));
}
__device__ __forceinline__ void mma_f16(float* c, const uint32_t* a, const uint32_t* b) {
    asm volatile(
        "mma.sync.aligned.m16n8k16.row.col.f32.f16.f16.f32 "
        "{%0,%1,%2,%3},{%4,%5,%6,%7},{%8,%9},{%0,%1,%2,%3};"
        : "+f"(c[0]), "+f"(c[1]), "+f"(c[2]), "+f"(c[3])
        : "r"(a[0]), "r"(a[1]), "r"(a[2]), "r"(a[3]), "r"(b[0]), "r"(b[1]));
}
#define CP16(dst, src) \
    asm volatile("cp.async.cg.shared.global [%0], [%1], 16;" :: "r"(dst), "l"(src))
#define CPCOMMIT() asm volatile("cp.async.commit_group;" ::: "memory")
#define CPWAIT1()  asm volatile("cp.async.wait_group 1;" ::: "memory")

__device__ __forceinline__ unsigned pk2h(__half a, __half b) {
    __half2 t = __halves2half2(a, b);
    unsigned r; memcpy(&r, &t, 4); return r;
}

// ============================ reset / gate ===============================
__global__ void k_reset() {
    if (threadIdx.x < NEXP) g_cnt[threadIdx.x] = 0;
}

__global__ void k_gate(const float* __restrict__ x, const float* __restrict__ gateW) {
    int gwarp = (blockIdx.x * blockDim.x + threadIdx.x) >> 5;
    int lane  = threadIdx.x & 31;
    if (gwarp >= TOK) return;
    const float* xr = x + (size_t)gwarp * DDIM;
    float xv[32];
#pragma unroll
    for (int i = 0; i < 32; i++) xv[i] = xr[lane + 32 * i];
    float logit[NEXP];
#pragma unroll
    for (int e = 0; e < NEXP; e++) {
        const float* wr = gateW + e * DDIM;
        float acc = 0.f;
#pragma unroll
        for (int i = 0; i < 32; i++) acc += xv[i] * wr[lane + 32 * i];
#pragma unroll
        for (int o = 16; o > 0; o >>= 1) acc += __shfl_xor_sync(0xffffffffu, acc, o);
        logit[e] = acc;
    }
    if (lane == 0) {
        float m = logit[0];
#pragma unroll
        for (int e = 1; e < NEXP; e++) m = fmaxf(m, logit[e]);
        float p[NEXP], den = 0.f;
#pragma unroll
        for (int e = 0; e < NEXP; e++) { p[e] = expf(logit[e] - m); den += p[e]; }
        int i1 = 0;
#pragma unroll
        for (int e = 1; e < NEXP; e++) if (p[e] > p[i1]) i1 = e;
        int i2 = (i1 == 0) ? 1 : 0;
#pragma unroll
        for (int e = 0; e < NEXP; e++) if (e != i2 && e != i1 && p[e] > p[i2]) i2 = e;
        int pos1 = atomicAdd(&g_cnt[i1], 1);
        int r1 = i1 * TOK + pos1;
        g_tok[r1] = gwarp;
        g_rowof[2 * gwarp + 0] = r1;
        g_gw[2 * gwarp + 0] = p[i1] / den;
        int pos2 = atomicAdd(&g_cnt[i2], 1);
        int r2 = i2 * TOK + pos2;
        g_tok[r2] = gwarp;
        g_rowof[2 * gwarp + 1] = r2;
        g_gw[2 * gwarp + 1] = p[i2] / den;
    }
}

// ===================== weight transpose (fp16) ===========================
// src z-block: [R?][C] fp32 with C = output-row dim; dst row remap via goff.
__global__ __launch_bounds__(256) void k_transplit(
    const float* __restrict__ src, int dst_id, size_t extra,
    int R, int C, size_t sstride, size_t dstride, int goff)
{
    __shared__ float tile[32][33];
    __half* dst = (dst_id == 0) ? g_wgT : g_w2T;
    dst += extra;

    int z = blockIdx.z;
    const float* s = src + (size_t)z * sstride;
    size_t dbase = (size_t)z * dstride;
    int c0 = blockIdx.x * 32, r0 = blockIdx.y * 32;
    int tx = threadIdx.x & 31, ty = threadIdx.x >> 5;
#pragma unroll
    for (int i = 0; i < 4; i++)
        tile[ty + 8 * i][tx] = s[(size_t)(r0 + ty + 8 * i) * C + c0 + tx];
    __syncthreads();
#pragma unroll
    for (int i = 0; i < 4; i++) {
        float v = tile[tx][ty + 8 * i];
        int r = c0 + ty + 8 * i;              // output row (F-index)
        int rr = (goff >= 0) ? (((r >> 5) << 6) + goff + (r & 31)) : r;
        size_t o = dbase + (size_t)rr * R + r0 + tx;
        dst[o] = __float2half_rn(v);
    }
}

__global__ void k_xsplit(const float* __restrict__ x) {
    int i = blockIdx.x * blockDim.x + threadIdx.x;
    g_x[i] = __float2half_rn(x[i]);
}

// ============================ GEMM tiles ================================
#define LDT 40          // smem row stride in fp16 elems (80B, conflict-free ldmatrix)
#define NSTG 3

// ---- GEMM1: 128(M) x 128(W'-rows) x 32, warps 4(M) x 2(N) ----
#define G1_A    0
#define G1_B    5120                  // 128 rows x LDT
#define G1_STG  10240                 // elems / stage
#define G1_STGB (G1_STG * 2)          // 20480 bytes / stage
#define G1_SMEM (NSTG * G1_STGB + 512)

__global__ __launch_bounds__(256, 2) void k_gemm1() {
    const int z   = blockIdx.z;
    const int m0  = blockIdx.y * 128;
    const int n0p = blockIdx.x * 128;     // W' row base
    const int M   = (z < NEXP) ? g_cnt[z] : TOK;
    if (m0 >= M) return;
    const size_t rowbase = (z < NEXP) ? ((size_t)z * TOK + m0) : ((size_t)ROWCAP + m0);

    extern __shared__ __align__(16) char sm[];
    int* stok = (int*)(sm + NSTG * G1_STGB);
    const int tid = threadIdx.x;
    if (tid < 128) {
        int r = m0 + tid; if (r > M - 1) r = M - 1;
        stok[tid] = (z < NEXP) ? g_tok[z * TOK + r] : r;
    }
    __syncthreads();

    const uint32_t sbu = smem_u32(sm);
    const int ra = tid >> 2, c4 = tid & 3;
    const int tA0 = stok[ra], tA1 = stok[64 + ra];
    const __half* sx0 = g_x + (size_t)tA0 * DDIM + c4 * 8;
    const __half* sx1 = g_x + (size_t)tA1 * DDIM + c4 * 8;
    const size_t bsrc = ((size_t)z * 2 * FDIM + n0p + ra) * DDIM + c4 * 8;
    const __half *sB0 = g_wgT + bsrc, *sB1 = sB0 + (size_t)64 * DDIM;

    const uint32_t dA0 = (G1_A + ra * LDT + c4 * 8) * 2;
    const uint32_t dA1 = dA0 + 64 * LDT * 2;
    const uint32_t dB0 = (G1_B + ra * LDT + c4 * 8) * 2;
    const uint32_t dB1 = dB0 + 64 * LDT * 2;

    const int lane = tid & 31, w = tid >> 5;
    const int wm = w >> 1, wn = w & 1;
    const int qr = lane >> 2, qc = lane & 3;
    const uint32_t aoff = ((wm * 32 + (lane & 15)) * LDT + (lane >> 4) * 8) * 2;
    const uint32_t boff = (G1_B + (wn * 64 + (lane & 7) + ((lane >> 4) & 1) * 8) * LDT
                           + ((lane >> 3) & 1) * 8) * 2;

    float acc[2][8][4] = {};

#define G1_LOAD(it) do { \
    const int k0 = (it) * 32; \
    const uint32_t db = sbu + ((it) % NSTG) * G1_STGB; \
    CP16(db + dA0, sx0 + k0); \
    CP16(db + dA1, sx1 + k0); \
    CP16(db + dB0, sB0 + k0); \
    CP16(db + dB1, sB1 + k0); \
    CPCOMMIT(); \
} while (0)

    G1_LOAD(0);
    G1_LOAD(1);

    const int NIT = DDIM / 32;
    for (int it = 0; it < NIT; it++) {
        CPWAIT1();
        __syncthreads();
        if (it + 2 < NIT) G1_LOAD(it + 2); else CPCOMMIT();
        const uint32_t stg = sbu + (it % NSTG) * G1_STGB;
#pragma unroll
        for (int ks = 0; ks < 32; ks += 16) {
            uint32_t ah[2][4];
#pragma unroll
            for (int mt = 0; mt < 2; mt++)
                ldsm4(ah[mt], stg + aoff + mt * (16 * LDT * 2) + ks * 2);
#pragma unroll
            for (int nh = 0; nh < 4; nh++) {
                uint32_t bb[4];
                ldsm4(bb, stg + boff + nh * (16 * LDT * 2) + ks * 2);
#pragma unroll
                for (int t = 0; t < 2; t++) {
                    const int nt = nh * 2 + t;
#pragma unroll
                    for (int mt = 0; mt < 2; mt++)
                        mma_f16(acc[mt][nt], ah[mt], bb + 2 * t);
                }
            }
        }
    }
#undef G1_LOAD

    // epilogue: GLU pairing in-register: g = acc[mt][nt], u = acc[mt][nt+4]
    const int fb = blockIdx.x * 64 + wn * 32;
#pragma unroll
    for (int mt = 0; mt < 2; mt++)
#pragma unroll
        for (int nt = 0; nt < 4; nt++) {
            const int R = wm * 32 + mt * 16 + qr;
            const int C = fb + nt * 8 + 2 * qc;
#pragma unroll
            for (int half = 0; half < 2; half++) {
                const int r = R + half * 8;
                float g0 = acc[mt][nt][2 * half],     u0 = acc[mt][nt + 4][2 * half];
                float g1 = acc[mt][nt][2 * half + 1], u1 = acc[mt][nt + 4][2 * half + 1];
                float o0 = g0 / (1.f + __expf(-g0)) * u0;
                float o1 = g1 / (1.f + __expf(-g1)) * u1;
                const size_t idx = (rowbase + r) * (size_t)FDIM + C;
                *(unsigned*)&g_h[idx] = pk2h(__float2half_rn(o0), __float2half_rn(o1));
            }
        }
}

// ---- GEMM2: 128 x 64 x 32, warps 4 x 2 over (32M x 32N) ----
#define G2_A    0
#define G2_B    5120
#define G2_STG  7680
#define G2_STGB (G2_STG * 2)
#define G2_SMEM (NSTG * G2_STGB)

__global__ __launch_bounds__(256, 2) void k_gemm2() {
    const int z  = blockIdx.z;
    const int m0 = blockIdx.y * 128;
    const int n0 = blockIdx.x * 64;
    const int M  = (z < NEXP) ? g_cnt[z] : TOK;
    if (m0 >= M) return;
    const size_t rowbase = (z < NEXP) ? ((size_t)z * TOK + m0) : ((size_t)ROWCAP + m0);

    extern __shared__ __align__(16) char sm[];
    const uint32_t sbu = smem_u32(sm);
    const int tid = threadIdx.x;
    const int ra = tid >> 2, c4 = tid & 3;

    const __half* sa0 = g_h + (rowbase + ra) * (size_t)FDIM + c4 * 8;
    const __half* sa1 = g_h + (rowbase + 64 + ra) * (size_t)FDIM + c4 * 8;
    const size_t bsrc = ((size_t)z * DDIM + n0 + ra) * FDIM + c4 * 8;
    const __half* sB = g_w2T + bsrc;
    const bool bok = (ra < 64);   // B tile has 64 rows; threads 0..255 -> ra 0..63 all valid

    const uint32_t dA0 = (G2_A + ra * LDT + c4 * 8) * 2;
    const uint32_t dA1 = dA0 + 64 * LDT * 2;
    const uint32_t dB  = (G2_B + ra * LDT + c4 * 8) * 2;

    const int lane = tid & 31, w = tid >> 5;
    const int wm = w >> 1, wn = w & 1;
    const int qr = lane >> 2, qc = lane & 3;
    const uint32_t aoff = ((wm * 32 + (lane & 15)) * LDT + (lane >> 4) * 8) * 2;
    const uint32_t boff = (G2_B + (wn * 32 + (lane & 7) + ((lane >> 4) & 1) * 8) * LDT
                           + ((lane >> 3) & 1) * 8) * 2;

    float acc[2][4][4] = {};

#define G2_LOAD(it) do { \
    const int k0 = (it) * 32; \
    const uint32_t db = sbu + ((it) % NSTG) * G2_STGB; \
    CP16(db + dA0, sa0 + k0); \
    CP16(db + dA1, sa1 + k0); \
    CP16(db + dB, sB + k0); \
    CPCOMMIT(); \
} while (0)

    G2_LOAD(0);
    G2_LOAD(1);

    const int NIT = FDIM / 32;
    for (int it = 0; it < NIT; it++) {
        CPWAIT1();
        __syncthreads();
        if (it + 2 < NIT) G2_LOAD(it + 2); else CPCOMMIT();
        const uint32_t stg = sbu + (it % NSTG) * G2_STGB;
#pragma unroll
        for (int ks = 0; ks < 32; ks += 16) {
            uint32_t ah[2][4];
#pragma unroll
            for (int mt = 0; mt < 2; mt++)
                ldsm4(ah[mt], stg + aoff + mt * (16 * LDT * 2) + ks * 2);
#pragma unroll
            for (int nh = 0; nh < 2; nh++) {
                uint32_t bb[4];
                ldsm4(bb, stg + boff + nh * (16 * LDT * 2) + ks * 2);
#pragma unroll
                for (int t = 0; t < 2; t++) {
                    const int nt = nh * 2 + t;
#pragma unroll
                    for (int mt = 0; mt < 2; mt++)
                        mma_f16(acc[mt][nt], ah[mt], bb + 2 * t);
                }
            }
        }
    }
#undef G2_LOAD
    (void)bok;

#pragma unroll
    for (int mt = 0; mt < 2; mt++)
#pragma unroll
        for (int nt = 0; nt < 4; nt++) {
            const int R = wm * 32 + mt * 16 + qr;
            const int C = wn * 32 + nt * 8 + 2 * qc;
#pragma unroll
            for (int half = 0; half < 2; half++) {
                const int r = R + half * 8;
                float2 o;
                o.x = acc[mt][nt][2 * half];
                o.y = acc[mt][nt][2 * half + 1];
                *(float2*)&g_orow[(rowbase + r) * (size_t)DDIM + n0 + C] = o;
            }
        }
}

// ============================ combine ===================================
__global__ void k_combine(float* __restrict__ out) {
    int idx = blockIdx.x * blockDim.x + threadIdx.x;
    if (idx >= TOK * DDIM) return;
    int t = idx >> 10;
    int d = idx & (DDIM - 1);
    float sh = g_orow[((size_t)ROWCAP + t) * DDIM + d];
    int   r0 = g_rowof[2 * t], r1 = g_rowof[2 * t + 1];
    float v = 0.0625f * sh
            + 0.5f * (g_gw[2 * t] * g_orow[(size_t)r0 * DDIM + d]
                    + g_gw[2 * t + 1] * g_orow[(size_t)r1 * DDIM + d]);
    out[idx] = v;
}

// ============================ launch ====================================
extern "C" void kernel_launch(void* const* d_in, const int* in_sizes, int n_in,
                              void* d_out, int out_size) {
    const float* x   = (const float*)d_in[0];
    const float* gW  = (const float*)d_in[1];
    const float* w1e = (const float*)d_in[2];
    const float* w3e = (const float*)d_in[3];
    const float* w2e = (const float*)d_in[4];
    const float* w1s = (const float*)d_in[5];
    const float* w3s = (const float*)d_in[6];
    const float* w2s = (const float*)d_in[7];
    float* out = (float*)d_out;

    cudaFuncSetAttribute(k_gemm1, cudaFuncAttributeMaxDynamicSharedMemorySize, G1_SMEM);
    cudaFuncSetAttribute(k_gemm2, cudaFuncAttributeMaxDynamicSharedMemorySize, G2_SMEM);

    k_reset<<<1, 32>>>();
    k_gate<<<TOK / 8, 256>>>(x, gW);
    k_xsplit<<<TOK * DDIM / 256, 256>>>(x);

    // routed: w1/w3 -> interleaved W' slots 0..7; w2 -> w2T slots 0..7
    k_transplit<<<dim3(FDIM / 32, DDIM / 32, NEXP), 256>>>(
        w1e, 0, 0, DDIM, FDIM, (size_t)DDIM * FDIM, (size_t)2 * FDIM * DDIM, 0);
    k_transplit<<<dim3(FDIM / 32, DDIM / 32, NEXP), 256>>>(
        w3e, 0, 0, DDIM, FDIM, (size_t)DDIM * FDIM, (size_t)2 * FDIM * DDIM, 32);
    k_transplit<<<dim3(DDIM / 32, FDIM / 32, NEXP), 256>>>(
        w2e, 1, 0, FDIM, DDIM, (size_t)FDIM * DDIM, (size_t)DDIM * FDIM, -1);
    // shared experts -> slot 8 (block-concatenated); per-z W' span = 1024 rows
    k_transplit<<<dim3(FSH / 32, DDIM / 32, NEXP), 256>>>(
        w1s, 0, (size_t)NEXP * 2 * FDIM * DDIM, DDIM, FSH, (size_t)DDIM * FSH,
        (size_t)1024 * DDIM, 0);
    k_transplit<<<dim3(FSH / 32, DDIM / 32, NEXP), 256>>>(
        w3s, 0, (size_t)NEXP * 2 * FDIM * DDIM, DDIM, FSH, (size_t)DDIM * FSH,
        (size_t)1024 * DDIM, 32);
    k_transplit<<<dim3(DDIM / 32, FDIM / 32, 1), 256>>>(
        w2s, 1, (size_t)NEXP * DDIM * FDIM, FDIM, DDIM, 0, 0, -1);

    k_gemm1<<<dim3(2 * FDIM / 128, TOK / 128, NSLOT), 256, G1_SMEM>>>();
    k_gemm2<<<dim3(DDIM / 64, TOK / 128, NSLOT), 256, G2_SMEM>>>();
    k_combine<<<(TOK * DDIM) / 256, 256>>>(out);
}